// round 4
// baseline (speedup 1.0000x reference)
#include <cuda_runtime.h>
#include <cuda_bf16.h>
#include <cstdint>
#include <float.h>

// Problem constants
#define N_ROWS  (64 * 2048)   // 131072
#define DDIM    128
#define KCODES  1024

// Output layout (fp32, concatenated in reference return order)
#define Q_OFF    ((size_t)0)
#define IND_OFF  ((size_t)16777216)
#define EMB_OFF  ((size_t)16908288)
#define NCS_OFF  ((size_t)17039360)
#define NEA_OFF  ((size_t)17040384)

#define DECAYF   0.99f
#define OMDF     0.01f
#define EPSF     1e-5f
#define KEPSF    0.01024f

#define SCREEN_T 0.6f
#define CAND_CAP 64

// ---------------------------------------------------------------------------
// Scratch (__device__ globals; no allocation allowed)
__device__ float    g_counts[KCODES];
__device__ float    g_embed_sum[KCODES * DDIM];
__device__ float    g_total;
__device__ float    g_ee[KCODES];
__device__ float    g_xx[N_ROWS];
__device__ int      g_idx[N_ROWS];
__device__ uint32_t g_X16[(size_t)N_ROWS * 64];  // bf16x2-packed X rows (32 MB)
__device__ uint4    g_E16[KCODES * 16];          // bf16 E, XOR-swizzled 16B units (256 KB)

// ---------------------------------------------------------------------------
__global__ void k_zero() {
    int t = blockIdx.x * blockDim.x + threadIdx.x;
    if (t < KCODES * DDIM) g_embed_sum[t] = 0.0f;
    if (t < KCODES) g_counts[t] = 0.0f;
    if (t == 0) g_total = 0.0f;
}

// Per-code squared norms
__global__ void k_ee(const float* __restrict__ embed) {
    int k = blockIdx.x;
    int t = threadIdx.x;  // 128
    float v = embed[(size_t)k * DDIM + t];
    v *= v;
    __shared__ float s[4];
    #pragma unroll
    for (int o = 16; o > 0; o >>= 1) v += __shfl_down_sync(0xffffffffu, v, o);
    if ((t & 31) == 0) s[t >> 5] = v;
    __syncthreads();
    if (t == 0) g_ee[k] = s[0] + s[1] + s[2] + s[3];
}

// Pack X rows to bf16x2 + compute row squared norms. 4 rows/block, 64 thr/row.
__global__ void k_packX(const float* __restrict__ x) {
    int tid = threadIdx.x;           // 256
    int r   = blockIdx.x * 4 + (tid >> 6);
    int i   = tid & 63;
    float2 v = ((const float2*)(x + (size_t)r * DDIM))[i];
    __nv_bfloat162 b = __float22bfloat162_rn(v);
    g_X16[(size_t)r * 64 + i] = *(uint32_t*)&b;
    float ss = v.x * v.x + v.y * v.y;
    #pragma unroll
    for (int o = 16; o > 0; o >>= 1) ss += __shfl_down_sync(0xffffffffu, ss, o);
    __shared__ float s[8];
    if ((tid & 31) == 0) s[tid >> 5] = ss;
    __syncthreads();
    if ((tid & 63) == 0) g_xx[r] = s[(tid >> 5)] + s[(tid >> 5) + 1];
}

// Pack E into bf16 with per-row XOR swizzle on 16B units: unit u of row r is
// stored at u ^ (r & 7). Makes ldmatrix (8 rows, 256B stride) conflict-free.
__global__ void k_packE(const float* __restrict__ embed) {
    int idx = blockIdx.x * blockDim.x + threadIdx.x;  // 16384 = 1024 rows * 16 units
    int r = idx >> 4;
    int u = idx & 15;
    const float* src = embed + (size_t)r * DDIM + u * 8;
    float4 a = ((const float4*)src)[0];
    float4 b = ((const float4*)src)[1];
    __nv_bfloat162 p0 = __float22bfloat162_rn(make_float2(a.x, a.y));
    __nv_bfloat162 p1 = __float22bfloat162_rn(make_float2(a.z, a.w));
    __nv_bfloat162 p2 = __float22bfloat162_rn(make_float2(b.x, b.y));
    __nv_bfloat162 p3 = __float22bfloat162_rn(make_float2(b.z, b.w));
    uint4 out;
    out.x = *(uint32_t*)&p0; out.y = *(uint32_t*)&p1;
    out.z = *(uint32_t*)&p2; out.w = *(uint32_t*)&p3;
    g_E16[r * 16 + (u ^ (r & 7))] = out;
}

// ---------------------------------------------------------------------------
__device__ __forceinline__ uint32_t smem_u32(const void* p) {
    uint32_t a;
    asm("{ .reg .u64 t; cvta.to.shared.u64 t, %1; cvt.u32.u64 %0, t; }" : "=r"(a) : "l"(p));
    return a;
}

#define MMA_BF16(accp, af, bb0, bb1) \
    asm volatile( \
        "mma.sync.aligned.m16n8k16.row.col.f32.bf16.bf16.f32 " \
        "{%0,%1,%2,%3}, {%4,%5,%6,%7}, {%8,%9}, {%0,%1,%2,%3};" \
        : "+f"((accp)[0]), "+f"((accp)[1]), "+f"((accp)[2]), "+f"((accp)[3]) \
        : "r"((af)[0]), "r"((af)[1]), "r"((af)[2]), "r"((af)[3]), \
          "r"(bb0), "r"(bb1))

// ---------------------------------------------------------------------------
// HMMA screening + exact fp32 rescore. CTA = 128 threads (4 warps),
// each warp owns 32 rows (A in registers), sweeps all 1024 codes.
// 8 independent accumulator chains (2 m-tiles x 4 n-tiles) per 32-code batch.
__global__ __launch_bounds__(128, 3) void k_score(const float* __restrict__ x,
                                                  const float* __restrict__ embed,
                                                  float* __restrict__ out) {
    __shared__ __align__(16) uint4 smE[1024];       // 16 KB: 64 codes x 128 bf16
    __shared__ float     sEE[64];
    __shared__ uint16_t  sCand[128 * CAND_CAP];     // 16 KB
    __shared__ uint32_t  sCnt[128];
    __shared__ int       fidx[128];

    const int tid  = threadIdx.x;
    const int wid  = tid >> 5;
    const int lane = tid & 31;
    const int g    = lane >> 2;       // row group within m16 tile
    const int tig  = lane & 3;        // col/thread-in-group
    const int rbase = blockIdx.x * 128 + wid * 32;

    sCnt[tid] = 0;

    // Load A fragments: 2 row-tiles x 8 k-steps x 4 regs (this warp's 32 rows).
    uint32_t afr[2][8][4];
    #pragma unroll
    for (int t2 = 0; t2 < 2; t2++) {
        const size_t rA = (size_t)(rbase + t2 * 16 + g) * 64;
        const size_t rB = rA + 8 * 64;
        #pragma unroll
        for (int ks = 0; ks < 8; ks++) {
            afr[t2][ks][0] = g_X16[rA + 8 * ks + tig];
            afr[t2][ks][1] = g_X16[rB + 8 * ks + tig];
            afr[t2][ks][2] = g_X16[rA + 8 * ks + 4 + tig];
            afr[t2][ks][3] = g_X16[rB + 8 * ks + 4 + tig];
        }
    }

    float rmax[4];
    #pragma unroll
    for (int i = 0; i < 4; i++) rmax[i] = -FLT_MAX;

    const uint32_t smEa = smem_u32(smE);
    // ldmatrix.x4 lane mapping: lanes 0-15 -> first n-tile pair's tile A rows
    // (0-7 k-low, 8-15 k-high), lanes 16-31 -> next tile.
    const int clo = ((lane >> 4) << 3) + (lane & 7);  // code-local base offset
    const int kb  = (lane >> 3) & 1;                  // k-half select

    for (int c = 0; c < 16; c++) {    // 16 chunks of 64 codes
        __syncthreads();
        {
            const uint4* ep = g_E16 + c * 1024;
            #pragma unroll
            for (int i = 0; i < 8; i++) smE[tid + i * 128] = ep[tid + i * 128];
            if (tid < 64) sEE[tid] = g_ee[c * 64 + tid];
        }
        __syncthreads();

        #pragma unroll
        for (int b = 0; b < 2; b++) {  // 2 batches of 32 codes
            const int cl0 = b * 32 + clo;        // tiles 0,1 of batch
            const int cl1 = cl0 + 16;            // tiles 2,3 of batch
            const uint32_t base0 = smEa + (cl0 << 8);
            const uint32_t base1 = smEa + (cl1 << 8);
            const int sw0 = cl0 & 7, sw1 = cl1 & 7;

            float acc[2][4][4];
            #pragma unroll
            for (int t2 = 0; t2 < 2; t2++)
                #pragma unroll
                for (int n2 = 0; n2 < 4; n2++)
                    #pragma unroll
                    for (int i = 0; i < 4; i++) acc[t2][n2][i] = 0.0f;

            #pragma unroll
            for (int ks = 0; ks < 8; ks++) {
                const uint32_t u = 2 * ks + kb;
                uint32_t b0, b1, b2, b3, b4, b5, b6, b7;
                asm volatile(
                    "ldmatrix.sync.aligned.m8n8.x4.shared.b16 {%0,%1,%2,%3}, [%4];"
                    : "=r"(b0), "=r"(b1), "=r"(b2), "=r"(b3)
                    : "r"(base0 + ((u ^ sw0) << 4)));
                asm volatile(
                    "ldmatrix.sync.aligned.m8n8.x4.shared.b16 {%0,%1,%2,%3}, [%4];"
                    : "=r"(b4), "=r"(b5), "=r"(b6), "=r"(b7)
                    : "r"(base1 + ((u ^ sw1) << 4)));
                #pragma unroll
                for (int t2 = 0; t2 < 2; t2++) {
                    MMA_BF16(acc[t2][0], afr[t2][ks], b0, b1);
                    MMA_BF16(acc[t2][1], afr[t2][ks], b2, b3);
                    MMA_BF16(acc[t2][2], afr[t2][ks], b4, b5);
                    MMA_BF16(acc[t2][3], afr[t2][ks], b6, b7);
                }
            }

            // Screening: dist-without-xx = 2*dot - ee (xx is row-constant).
            #pragma unroll
            for (int n2 = 0; n2 < 4; n2++) {
                const int le0   = b * 32 + n2 * 8 + 2 * tig;
                const int code0 = c * 64 + le0;
                const float ee0 = sEE[le0];
                const float ee1 = sEE[le0 + 1];
                #pragma unroll
                for (int t2 = 0; t2 < 2; t2++) {
                    #pragma unroll
                    for (int h = 0; h < 2; h++) {   // h=0: row g, h=1: row g+8
                        const int lr = wid * 32 + t2 * 16 + h * 8 + g;
                        float m = rmax[t2 * 2 + h];
                        const float s0 = 2.0f * acc[t2][n2][2 * h] - ee0;
                        if (s0 > m) m = s0;
                        if (s0 >= m - SCREEN_T) {
                            uint32_t n = atomicAdd(&sCnt[lr], 1u);
                            if (n < CAND_CAP) sCand[lr * CAND_CAP + n] = (uint16_t)code0;
                        }
                        const float s1 = 2.0f * acc[t2][n2][2 * h + 1] - ee1;
                        if (s1 > m) m = s1;
                        if (s1 >= m - SCREEN_T) {
                            uint32_t n = atomicAdd(&sCnt[lr], 1u);
                            if (n < CAND_CAP) sCand[lr * CAND_CAP + n] = (uint16_t)(code0 + 1);
                        }
                        rmax[t2 * 2 + h] = m;
                    }
                }
            }
        }

        // Tighten running max across the 4 lanes sharing each row.
        #pragma unroll
        for (int i = 0; i < 4; i++) {
            float v = rmax[i];
            v = fmaxf(v, __shfl_xor_sync(0xffffffffu, v, 1));
            v = fmaxf(v, __shfl_xor_sync(0xffffffffu, v, 2));
            rmax[i] = v;
        }
    }
    __syncthreads();

    // Exact fp32 rescore: one thread per row.
    {
        const int lr  = tid;
        const int row = blockIdx.x * 128 + lr;
        const float xx = g_xx[row];
        const uint32_t cnt = sCnt[lr];
        const float4* xr = (const float4*)(x + (size_t)row * DDIM);
        float bestv = -FLT_MAX;
        int   bestk = 0;
        const int nIt = (cnt <= CAND_CAP) ? (int)cnt : KCODES;
        for (int j = 0; j < nIt; j++) {
            const int k = (cnt <= CAND_CAP) ? (int)sCand[lr * CAND_CAP + j] : j;
            const float4* er = (const float4*)(embed + (size_t)k * DDIM);
            float a0 = 0.f, a1 = 0.f, a2 = 0.f, a3 = 0.f;
            #pragma unroll 8
            for (int i = 0; i < 32; i++) {
                float4 xa = xr[i], ea = er[i];
                a0 = fmaf(xa.x, ea.x, a0);
                a1 = fmaf(xa.y, ea.y, a1);
                a2 = fmaf(xa.z, ea.z, a2);
                a3 = fmaf(xa.w, ea.w, a3);
            }
            const float dot = (a0 + a1) + (a2 + a3);
            const float dist = (-xx + 2.0f * dot) - g_ee[k];
            if (dist > bestv || (dist == bestv && k < bestk)) { bestv = dist; bestk = k; }
        }
        fidx[lr] = bestk;
        g_idx[row] = bestk;
        out[IND_OFF + (size_t)row] = (float)bestk;
    }
    __syncthreads();

    // quantized = embed[idx] (coalesced float4 gather-copy)
    for (int v = tid; v < 128 * 32; v += 128) {
        const int r = v >> 5, seg = v & 31;
        const float4* ep = (const float4*)(embed + (size_t)fidx[r] * DDIM);
        ((float4*)out)[(size_t)(blockIdx.x * 128 + r) * 32 + seg] = ep[seg];
    }
}

// ---------------------------------------------------------------------------
// Scatter-add: counts[idx] += 1, embed_sum[idx] += x[row]. 4 rows per block.
__global__ void k_scatter(const float* __restrict__ x) {
    int row = blockIdx.x * 4 + (threadIdx.x >> 7);
    int d   = threadIdx.x & 127;
    int idx = g_idx[row];
    atomicAdd(&g_embed_sum[(size_t)idx * DDIM + d], x[(size_t)row * DDIM + d]);
    if (d == 0) atomicAdd(&g_counts[idx], 1.0f);
}

__global__ void k_c1(const float* __restrict__ cs, float* __restrict__ out) {
    int i = threadIdx.x;  // 1024
    float ncs = cs[i] * DECAYF + OMDF * g_counts[i];
    out[NCS_OFF + (size_t)i] = ncs;
    float v = ncs;
    #pragma unroll
    for (int o = 16; o > 0; o >>= 1) v += __shfl_down_sync(0xffffffffu, v, o);
    __shared__ float s[32];
    if ((i & 31) == 0) s[i >> 5] = v;
    __syncthreads();
    if (i < 32) {
        float w = s[i];
        #pragma unroll
        for (int o = 16; o > 0; o >>= 1) w += __shfl_down_sync(0xffffffffu, w, o);
        if (i == 0) g_total = w;
    }
}

__global__ void k_c2(const float* __restrict__ ea, float* __restrict__ out) {
    int k = blockIdx.x;
    int d = threadIdx.x;  // 128
    size_t off = (size_t)k * DDIM + d;
    float nea = ea[off] * DECAYF + OMDF * g_embed_sum[off];
    out[NEA_OFF + off] = nea;
    float total = g_total;
    float ncs   = out[NCS_OFF + (size_t)k];
    float sm    = (ncs + EPSF) / (total + KEPSF) * total;
    out[EMB_OFF + off] = nea / sm;
}

// ---------------------------------------------------------------------------
extern "C" void kernel_launch(void* const* d_in, const int* in_sizes, int n_in,
                              void* d_out, int out_size) {
    const float* x  = (const float*)d_in[0];
    const float* e  = (const float*)d_in[1];
    const float* ea = (const float*)d_in[2];
    const float* cs = (const float*)d_in[3];
    float* out = (float*)d_out;

    k_zero<<<(KCODES * DDIM + 255) / 256, 256>>>();
    k_ee<<<KCODES, 128>>>(e);
    k_packX<<<N_ROWS / 4, 256>>>(x);
    k_packE<<<64, 256>>>(e);
    k_score<<<N_ROWS / 128, 128>>>(x, e, out);
    k_scatter<<<N_ROWS / 4, 512>>>(x);
    k_c1<<<1, 1024>>>(cs, out);
    k_c2<<<KCODES, 128>>>(ea, out);
}

// round 5
// speedup vs baseline: 1.1421x; 1.1421x over previous
#include <cuda_runtime.h>
#include <cuda_bf16.h>
#include <cstdint>
#include <float.h>

// Problem constants
#define N_ROWS  (64 * 2048)   // 131072
#define DDIM    128
#define KCODES  1024

// Output layout (fp32, concatenated in reference return order)
#define Q_OFF    ((size_t)0)
#define IND_OFF  ((size_t)16777216)
#define EMB_OFF  ((size_t)16908288)
#define NCS_OFF  ((size_t)17039360)
#define NEA_OFF  ((size_t)17040384)

#define DECAYF   0.99f
#define OMDF     0.01f
#define EPSF     1e-5f
#define KEPSF    0.01024f

#define SCREEN_T 0.6f
#define CAND_CAP 64

// ---------------------------------------------------------------------------
// Scratch (__device__ globals; no allocation allowed)
__device__ float    g_counts[KCODES];
__device__ float    g_embed_sum[KCODES * DDIM];
__device__ float    g_total;
__device__ float    g_ee[KCODES];
__device__ float    g_xx[N_ROWS];
__device__ int      g_idx[N_ROWS];
__device__ uint32_t g_X16[(size_t)N_ROWS * 64];  // bf16x2-packed X rows (32 MB)
__device__ uint4    g_E16[KCODES * 16];          // bf16 E, XOR-swizzled 16B units (256 KB)

// ---------------------------------------------------------------------------
// Init: zero accumulators + per-code squared norms. Block k handles code k.
__global__ void k_init(const float* __restrict__ embed) {
    int k = blockIdx.x;       // 1024
    int t = threadIdx.x;      // 128
    g_embed_sum[(size_t)k * DDIM + t] = 0.0f;
    if (t == 0) g_counts[k] = 0.0f;
    if (k == 0 && t == 0) g_total = 0.0f;

    float v = embed[(size_t)k * DDIM + t];
    v *= v;
    __shared__ float s[4];
    #pragma unroll
    for (int o = 16; o > 0; o >>= 1) v += __shfl_down_sync(0xffffffffu, v, o);
    if ((t & 31) == 0) s[t >> 5] = v;
    __syncthreads();
    if (t == 0) g_ee[k] = s[0] + s[1] + s[2] + s[3];
}

// Pack X rows to bf16x2 + compute row squared norms. 4 rows/block, 64 thr/row.
__global__ void k_packX(const float* __restrict__ x) {
    int tid = threadIdx.x;           // 256
    int r   = blockIdx.x * 4 + (tid >> 6);
    int i   = tid & 63;
    float2 v = ((const float2*)(x + (size_t)r * DDIM))[i];
    __nv_bfloat162 b = __float22bfloat162_rn(v);
    g_X16[(size_t)r * 64 + i] = *(uint32_t*)&b;
    float ss = v.x * v.x + v.y * v.y;
    #pragma unroll
    for (int o = 16; o > 0; o >>= 1) ss += __shfl_down_sync(0xffffffffu, ss, o);
    __shared__ float s[8];
    if ((tid & 31) == 0) s[tid >> 5] = ss;
    __syncthreads();
    if ((tid & 63) == 0) g_xx[r] = s[(tid >> 5)] + s[(tid >> 5) + 1];
}

// Pack E into bf16 with per-row XOR swizzle on 16B units: unit u of row r is
// stored at u ^ (r & 7). Makes ldmatrix (8 rows, 256B stride) conflict-free.
__global__ void k_packE(const float* __restrict__ embed) {
    int idx = blockIdx.x * blockDim.x + threadIdx.x;  // 16384 = 1024 rows * 16 units
    int r = idx >> 4;
    int u = idx & 15;
    const float* src = embed + (size_t)r * DDIM + u * 8;
    float4 a = ((const float4*)src)[0];
    float4 b = ((const float4*)src)[1];
    __nv_bfloat162 p0 = __float22bfloat162_rn(make_float2(a.x, a.y));
    __nv_bfloat162 p1 = __float22bfloat162_rn(make_float2(a.z, a.w));
    __nv_bfloat162 p2 = __float22bfloat162_rn(make_float2(b.x, b.y));
    __nv_bfloat162 p3 = __float22bfloat162_rn(make_float2(b.z, b.w));
    uint4 out;
    out.x = *(uint32_t*)&p0; out.y = *(uint32_t*)&p1;
    out.z = *(uint32_t*)&p2; out.w = *(uint32_t*)&p3;
    g_E16[r * 16 + (u ^ (r & 7))] = out;
}

// ---------------------------------------------------------------------------
__device__ __forceinline__ uint32_t smem_u32(const void* p) {
    uint32_t a;
    asm("{ .reg .u64 t; cvta.to.shared.u64 t, %1; cvt.u32.u64 %0, t; }" : "=r"(a) : "l"(p));
    return a;
}

#define MMA_BF16(accp, af, bb0, bb1) \
    asm volatile( \
        "mma.sync.aligned.m16n8k16.row.col.f32.bf16.bf16.f32 " \
        "{%0,%1,%2,%3}, {%4,%5,%6,%7}, {%8,%9}, {%0,%1,%2,%3};" \
        : "+f"((accp)[0]), "+f"((accp)[1]), "+f"((accp)[2]), "+f"((accp)[3]) \
        : "r"((af)[0]), "r"((af)[1]), "r"((af)[2]), "r"((af)[3]), \
          "r"(bb0), "r"(bb1))

// ---------------------------------------------------------------------------
// HMMA screening + exact fp32 rescore. CTA = 128 threads (4 warps),
// each warp owns 32 rows (A in registers), sweeps all 1024 codes.
// 4 independent accumulator chains (2 m-tiles x 2 n-tiles), 16-code batches.
__global__ __launch_bounds__(128, 4) void k_score(const float* __restrict__ x,
                                                  const float* __restrict__ embed,
                                                  float* __restrict__ out) {
    __shared__ __align__(16) uint4 smE[1024];       // 16 KB: 64 codes x 128 bf16
    __shared__ float     sEE[64];
    __shared__ uint16_t  sCand[128 * CAND_CAP];     // 16 KB
    __shared__ uint32_t  sCnt[128];
    __shared__ int       fidx[128];

    const int tid  = threadIdx.x;
    const int wid  = tid >> 5;
    const int lane = tid & 31;
    const int g    = lane >> 2;       // row group within m16 tile
    const int tig  = lane & 3;        // col/thread-in-group
    const int rbase = blockIdx.x * 128 + wid * 32;

    sCnt[tid] = 0;

    // Load A fragments: 2 row-tiles x 8 k-steps x 4 regs (this warp's 32 rows).
    uint32_t afr[2][8][4];
    #pragma unroll
    for (int t2 = 0; t2 < 2; t2++) {
        const size_t rA = (size_t)(rbase + t2 * 16 + g) * 64;
        const size_t rB = rA + 8 * 64;
        #pragma unroll
        for (int ks = 0; ks < 8; ks++) {
            afr[t2][ks][0] = g_X16[rA + 8 * ks + tig];
            afr[t2][ks][1] = g_X16[rB + 8 * ks + tig];
            afr[t2][ks][2] = g_X16[rA + 8 * ks + 4 + tig];
            afr[t2][ks][3] = g_X16[rB + 8 * ks + 4 + tig];
        }
    }

    float rmax[4];
    #pragma unroll
    for (int i = 0; i < 4; i++) rmax[i] = -FLT_MAX;

    const uint32_t smEa = smem_u32(smE);
    // ldmatrix.x4 lane mapping: group = lane>>3 selects matrix
    //   m0: codes 0-7 k-low, m1: codes 0-7 k-high, m2: codes 8-15 k-low, m3: k-high
    const int row8  = lane & 7;
    const int ctile = (lane >> 4) & 1;   // code half within 16-code batch
    const int khalf = (lane >> 3) & 1;   // k half within k16 step

    for (int c = 0; c < 16; c++) {    // 16 chunks of 64 codes
        __syncthreads();
        {
            const uint4* ep = g_E16 + c * 1024;
            #pragma unroll
            for (int i = 0; i < 8; i++) smE[tid + i * 128] = ep[tid + i * 128];
            if (tid < 64) sEE[tid] = g_ee[c * 64 + tid];
        }
        __syncthreads();

        #pragma unroll
        for (int b = 0; b < 4; b++) {  // 4 batches of 16 codes
            // per-lane ldmatrix source row: code (b*16 + ctile*8 + row8)
            const uint32_t rowaddr = smEa + ((b * 16 + ctile * 8 + row8) << 8);

            float acc[2][2][4];
            #pragma unroll
            for (int t2 = 0; t2 < 2; t2++)
                #pragma unroll
                for (int n2 = 0; n2 < 2; n2++)
                    #pragma unroll
                    for (int i = 0; i < 4; i++) acc[t2][n2][i] = 0.0f;

            #pragma unroll
            for (int ks = 0; ks < 8; ks++) {
                uint32_t b0, b1, b2, b3;
                asm volatile(
                    "ldmatrix.sync.aligned.m8n8.x4.shared.b16 {%0,%1,%2,%3}, [%4];"
                    : "=r"(b0), "=r"(b1), "=r"(b2), "=r"(b3)
                    : "r"(rowaddr + (((2 * ks + khalf) ^ row8) << 4)));
                #pragma unroll
                for (int t2 = 0; t2 < 2; t2++) {
                    MMA_BF16(acc[t2][0], afr[t2][ks], b0, b1);
                    MMA_BF16(acc[t2][1], afr[t2][ks], b2, b3);
                }
            }

            // Screening: dist-without-xx = 2*dot - ee (xx is row-constant).
            #pragma unroll
            for (int n2 = 0; n2 < 2; n2++) {
                const int le0   = b * 16 + n2 * 8 + 2 * tig;
                const int code0 = c * 64 + le0;
                const float ee0 = sEE[le0];
                const float ee1 = sEE[le0 + 1];
                #pragma unroll
                for (int t2 = 0; t2 < 2; t2++) {
                    #pragma unroll
                    for (int h = 0; h < 2; h++) {   // h=0: row g, h=1: row g+8
                        const int lr = wid * 32 + t2 * 16 + h * 8 + g;
                        float m = rmax[t2 * 2 + h];
                        const float s0 = 2.0f * acc[t2][n2][2 * h] - ee0;
                        if (s0 > m) m = s0;
                        if (s0 >= m - SCREEN_T) {
                            uint32_t n = atomicAdd(&sCnt[lr], 1u);
                            if (n < CAND_CAP) sCand[lr * CAND_CAP + n] = (uint16_t)code0;
                        }
                        const float s1 = 2.0f * acc[t2][n2][2 * h + 1] - ee1;
                        if (s1 > m) m = s1;
                        if (s1 >= m - SCREEN_T) {
                            uint32_t n = atomicAdd(&sCnt[lr], 1u);
                            if (n < CAND_CAP) sCand[lr * CAND_CAP + n] = (uint16_t)(code0 + 1);
                        }
                        rmax[t2 * 2 + h] = m;
                    }
                }
            }
        }

        // Tighten running max across the 4 lanes sharing each row.
        #pragma unroll
        for (int i = 0; i < 4; i++) {
            float v = rmax[i];
            v = fmaxf(v, __shfl_xor_sync(0xffffffffu, v, 1));
            v = fmaxf(v, __shfl_xor_sync(0xffffffffu, v, 2));
            rmax[i] = v;
        }
    }
    __syncthreads();

    // Exact fp32 rescore: one thread per row.
    {
        const int lr  = tid;
        const int row = blockIdx.x * 128 + lr;
        const float xx = g_xx[row];
        const uint32_t cnt = sCnt[lr];
        const float4* xr = (const float4*)(x + (size_t)row * DDIM);
        float bestv = -FLT_MAX;
        int   bestk = 0;
        const int nIt = (cnt <= CAND_CAP) ? (int)cnt : KCODES;
        for (int j = 0; j < nIt; j++) {
            const int k = (cnt <= CAND_CAP) ? (int)sCand[lr * CAND_CAP + j] : j;
            const float4* er = (const float4*)(embed + (size_t)k * DDIM);
            float a0 = 0.f, a1 = 0.f, a2 = 0.f, a3 = 0.f;
            #pragma unroll 8
            for (int i = 0; i < 32; i++) {
                float4 xa = xr[i], ea = er[i];
                a0 = fmaf(xa.x, ea.x, a0);
                a1 = fmaf(xa.y, ea.y, a1);
                a2 = fmaf(xa.z, ea.z, a2);
                a3 = fmaf(xa.w, ea.w, a3);
            }
            const float dot = (a0 + a1) + (a2 + a3);
            const float dist = (-xx + 2.0f * dot) - g_ee[k];
            if (dist > bestv || (dist == bestv && k < bestk)) { bestv = dist; bestk = k; }
        }
        fidx[lr] = bestk;
        g_idx[row] = bestk;
        out[IND_OFF + (size_t)row] = (float)bestk;
    }
    __syncthreads();

    // quantized = embed[idx] (coalesced float4 gather-copy)
    for (int v = tid; v < 128 * 32; v += 128) {
        const int r = v >> 5, seg = v & 31;
        const float4* ep = (const float4*)(embed + (size_t)fidx[r] * DDIM);
        ((float4*)out)[(size_t)(blockIdx.x * 128 + r) * 32 + seg] = ep[seg];
    }
}

// ---------------------------------------------------------------------------
// Scatter-add: counts[idx] += 1, embed_sum[idx] += x[row]. 4 rows per block.
__global__ void k_scatter(const float* __restrict__ x) {
    int row = blockIdx.x * 4 + (threadIdx.x >> 7);
    int d   = threadIdx.x & 127;
    int idx = g_idx[row];
    atomicAdd(&g_embed_sum[(size_t)idx * DDIM + d], x[(size_t)row * DDIM + d]);
    if (d == 0) atomicAdd(&g_counts[idx], 1.0f);
}

__global__ void k_c1(const float* __restrict__ cs, float* __restrict__ out) {
    int i = threadIdx.x;  // 1024
    float ncs = cs[i] * DECAYF + OMDF * g_counts[i];
    out[NCS_OFF + (size_t)i] = ncs;
    float v = ncs;
    #pragma unroll
    for (int o = 16; o > 0; o >>= 1) v += __shfl_down_sync(0xffffffffu, v, o);
    __shared__ float s[32];
    if ((i & 31) == 0) s[i >> 5] = v;
    __syncthreads();
    if (i < 32) {
        float w = s[i];
        #pragma unroll
        for (int o = 16; o > 0; o >>= 1) w += __shfl_down_sync(0xffffffffu, w, o);
        if (i == 0) g_total = w;
    }
}

__global__ void k_c2(const float* __restrict__ ea, float* __restrict__ out) {
    int k = blockIdx.x;
    int d = threadIdx.x;  // 128
    size_t off = (size_t)k * DDIM + d;
    float nea = ea[off] * DECAYF + OMDF * g_embed_sum[off];
    out[NEA_OFF + off] = nea;
    float total = g_total;
    float ncs   = out[NCS_OFF + (size_t)k];
    float sm    = (ncs + EPSF) / (total + KEPSF) * total;
    out[EMB_OFF + off] = nea / sm;
}

// ---------------------------------------------------------------------------
extern "C" void kernel_launch(void* const* d_in, const int* in_sizes, int n_in,
                              void* d_out, int out_size) {
    const float* x  = (const float*)d_in[0];
    const float* e  = (const float*)d_in[1];
    const float* ea = (const float*)d_in[2];
    const float* cs = (const float*)d_in[3];
    float* out = (float*)d_out;

    k_init<<<KCODES, 128>>>(e);                 // launch 1
    k_packX<<<N_ROWS / 4, 256>>>(x);            // launch 2
    k_packE<<<64, 256>>>(e);                    // launch 3
    k_score<<<N_ROWS / 128, 128>>>(x, e, out);  // launch 4  (ncu capture slot)
    k_scatter<<<N_ROWS / 4, 512>>>(x);          // launch 5
    k_c1<<<1, 1024>>>(cs, out);                 // launch 6
    k_c2<<<KCODES, 128>>>(ea, out);             // launch 7
}

// round 6
// speedup vs baseline: 1.1826x; 1.0354x over previous
#include <cuda_runtime.h>
#include <cuda_bf16.h>
#include <cstdint>
#include <float.h>

// Problem constants
#define N_ROWS  (64 * 2048)   // 131072
#define DDIM    128
#define KCODES  1024

// Output layout (fp32, concatenated in reference return order)
#define Q_OFF    ((size_t)0)
#define IND_OFF  ((size_t)16777216)
#define EMB_OFF  ((size_t)16908288)
#define NCS_OFF  ((size_t)17039360)
#define NEA_OFF  ((size_t)17040384)

#define DECAYF   0.99f
#define OMDF     0.01f
#define EPSF     1e-5f
#define KEPSF    0.01024f

#define SCREEN_T 0.6f
#define CAND_CAP 64

// ---------------------------------------------------------------------------
// Scratch (__device__ globals; no allocation allowed)
__device__ float    g_counts[KCODES];
__device__ float    g_embed_sum[KCODES * DDIM];
__device__ float    g_total;
__device__ float    g_ee[KCODES];
__device__ float    g_xx[N_ROWS];
__device__ int      g_idx[N_ROWS];
__device__ uint32_t g_X16[(size_t)N_ROWS * 64];  // bf16x2-packed X rows (32 MB)
__device__ uint4    g_E16[KCODES * 16];          // bf16 E, XOR-swizzled 16B units (256 KB)

// ---------------------------------------------------------------------------
// Init: zero accumulators + per-code squared norms. Block k handles code k.
__global__ void k_init(const float* __restrict__ embed) {
    int k = blockIdx.x;       // 1024
    int t = threadIdx.x;      // 128
    g_embed_sum[(size_t)k * DDIM + t] = 0.0f;
    if (t == 0) g_counts[k] = 0.0f;
    if (k == 0 && t == 0) g_total = 0.0f;

    float v = embed[(size_t)k * DDIM + t];
    v *= v;
    __shared__ float s[4];
    #pragma unroll
    for (int o = 16; o > 0; o >>= 1) v += __shfl_down_sync(0xffffffffu, v, o);
    if ((t & 31) == 0) s[t >> 5] = v;
    __syncthreads();
    if (t == 0) g_ee[k] = s[0] + s[1] + s[2] + s[3];
}

// Pack X rows to bf16x2 + compute row squared norms. 4 rows/block, 64 thr/row.
__global__ void k_packX(const float* __restrict__ x) {
    int tid = threadIdx.x;           // 256
    int r   = blockIdx.x * 4 + (tid >> 6);
    int i   = tid & 63;
    float2 v = ((const float2*)(x + (size_t)r * DDIM))[i];
    __nv_bfloat162 b = __float22bfloat162_rn(v);
    g_X16[(size_t)r * 64 + i] = *(uint32_t*)&b;
    float ss = v.x * v.x + v.y * v.y;
    #pragma unroll
    for (int o = 16; o > 0; o >>= 1) ss += __shfl_down_sync(0xffffffffu, ss, o);
    __shared__ float s[8];
    if ((tid & 31) == 0) s[tid >> 5] = ss;
    __syncthreads();
    if ((tid & 63) == 0) g_xx[r] = s[(tid >> 5)] + s[(tid >> 5) + 1];
}

// Pack E into bf16 with per-row XOR swizzle on 16B units: unit u of row r is
// stored at u ^ (r & 7). Makes ldmatrix (8 rows, 256B stride) conflict-free.
__global__ void k_packE(const float* __restrict__ embed) {
    int idx = blockIdx.x * blockDim.x + threadIdx.x;  // 16384 = 1024 rows * 16 units
    int r = idx >> 4;
    int u = idx & 15;
    const float* src = embed + (size_t)r * DDIM + u * 8;
    float4 a = ((const float4*)src)[0];
    float4 b = ((const float4*)src)[1];
    __nv_bfloat162 p0 = __float22bfloat162_rn(make_float2(a.x, a.y));
    __nv_bfloat162 p1 = __float22bfloat162_rn(make_float2(a.z, a.w));
    __nv_bfloat162 p2 = __float22bfloat162_rn(make_float2(b.x, b.y));
    __nv_bfloat162 p3 = __float22bfloat162_rn(make_float2(b.z, b.w));
    uint4 out;
    out.x = *(uint32_t*)&p0; out.y = *(uint32_t*)&p1;
    out.z = *(uint32_t*)&p2; out.w = *(uint32_t*)&p3;
    g_E16[r * 16 + (u ^ (r & 7))] = out;
}

// ---------------------------------------------------------------------------
__device__ __forceinline__ uint32_t smem_u32(const void* p) {
    uint32_t a;
    asm("{ .reg .u64 t; cvta.to.shared.u64 t, %1; cvt.u32.u64 %0, t; }" : "=r"(a) : "l"(p));
    return a;
}

#define MMA_BF16(accp, af, bb0, bb1) \
    asm volatile( \
        "mma.sync.aligned.m16n8k16.row.col.f32.bf16.bf16.f32 " \
        "{%0,%1,%2,%3}, {%4,%5,%6,%7}, {%8,%9}, {%0,%1,%2,%3};" \
        : "+f"((accp)[0]), "+f"((accp)[1]), "+f"((accp)[2]), "+f"((accp)[3]) \
        : "r"((af)[0]), "r"((af)[1]), "r"((af)[2]), "r"((af)[3]), \
          "r"(bb0), "r"(bb1))

// ---------------------------------------------------------------------------
// HMMA screening + exact fp32 rescore. CTA = 128 threads (4 warps),
// each warp owns 32 rows (A in registers), sweeps all 1024 codes.
__global__ __launch_bounds__(128, 4) void k_score(const float* __restrict__ x,
                                                  const float* __restrict__ embed,
                                                  float* __restrict__ out) {
    __shared__ __align__(16) uint4 smE[1024];       // 16 KB: 64 codes x 128 bf16
    __shared__ float     sEE[64];
    __shared__ uint16_t  sCand[128 * CAND_CAP];     // 16 KB
    __shared__ uint32_t  sCnt[128];
    __shared__ int       fidx[128];

    const int tid  = threadIdx.x;
    const int wid  = tid >> 5;
    const int lane = tid & 31;
    const int g    = lane >> 2;       // row group within m16 tile
    const int tig  = lane & 3;        // col/thread-in-group
    const int rbase = blockIdx.x * 128 + wid * 32;

    sCnt[tid] = 0;

    // Load A fragments: 2 row-tiles x 8 k-steps x 4 regs (this warp's 32 rows).
    uint32_t afr[2][8][4];
    #pragma unroll
    for (int t2 = 0; t2 < 2; t2++) {
        const size_t rA = (size_t)(rbase + t2 * 16 + g) * 64;
        const size_t rB = rA + 8 * 64;
        #pragma unroll
        for (int ks = 0; ks < 8; ks++) {
            afr[t2][ks][0] = g_X16[rA + 8 * ks + tig];
            afr[t2][ks][1] = g_X16[rB + 8 * ks + tig];
            afr[t2][ks][2] = g_X16[rA + 8 * ks + 4 + tig];
            afr[t2][ks][3] = g_X16[rB + 8 * ks + 4 + tig];
        }
    }

    float rmax[4];
    #pragma unroll
    for (int i = 0; i < 4; i++) rmax[i] = -FLT_MAX;

    const uint32_t smEa = smem_u32(smE);
    const int row8  = lane & 7;
    const int ctile = (lane >> 4) & 1;   // code half within 16-code batch
    const int khalf = (lane >> 3) & 1;   // k half within k16 step

    for (int c = 0; c < 16; c++) {    // 16 chunks of 64 codes
        __syncthreads();
        {
            const uint4* ep = g_E16 + c * 1024;
            #pragma unroll
            for (int i = 0; i < 8; i++) smE[tid + i * 128] = ep[tid + i * 128];
            if (tid < 64) sEE[tid] = g_ee[c * 64 + tid];
        }
        __syncthreads();

        #pragma unroll
        for (int b = 0; b < 4; b++) {  // 4 batches of 16 codes
            const uint32_t rowaddr = smEa + ((b * 16 + ctile * 8 + row8) << 8);

            float acc[2][2][4];
            #pragma unroll
            for (int t2 = 0; t2 < 2; t2++)
                #pragma unroll
                for (int n2 = 0; n2 < 2; n2++)
                    #pragma unroll
                    for (int i = 0; i < 4; i++) acc[t2][n2][i] = 0.0f;

            #pragma unroll
            for (int ks = 0; ks < 8; ks++) {
                uint32_t b0, b1, b2, b3;
                asm volatile(
                    "ldmatrix.sync.aligned.m8n8.x4.shared.b16 {%0,%1,%2,%3}, [%4];"
                    : "=r"(b0), "=r"(b1), "=r"(b2), "=r"(b3)
                    : "r"(rowaddr + (((2 * ks + khalf) ^ row8) << 4)));
                #pragma unroll
                for (int t2 = 0; t2 < 2; t2++) {
                    MMA_BF16(acc[t2][0], afr[t2][ks], b0, b1);
                    MMA_BF16(acc[t2][1], afr[t2][ks], b2, b3);
                }
            }

            // Branchless stale-max screening: threshold from rmax BEFORE this
            // batch (rmax only grows -> guaranteed superset of final-max set).
            float thr[4];
            #pragma unroll
            for (int i = 0; i < 4; i++) thr[i] = rmax[i] - SCREEN_T;

            #pragma unroll
            for (int n2 = 0; n2 < 2; n2++) {
                const int le0   = b * 16 + n2 * 8 + 2 * tig;
                const int code0 = c * 64 + le0;
                const float ee0 = sEE[le0];
                const float ee1 = sEE[le0 + 1];
                #pragma unroll
                for (int t2 = 0; t2 < 2; t2++) {
                    #pragma unroll
                    for (int h = 0; h < 2; h++) {   // h=0: row g, h=1: row g+8
                        const int ci = t2 * 2 + h;
                        const int lr = wid * 32 + t2 * 16 + h * 8 + g;
                        const float s0 = fmaf(2.0f, acc[t2][n2][2 * h], -ee0);
                        const float s1 = fmaf(2.0f, acc[t2][n2][2 * h + 1], -ee1);
                        if (s0 >= thr[ci]) {
                            uint32_t n = atomicAdd(&sCnt[lr], 1u);
                            if (n < CAND_CAP) sCand[lr * CAND_CAP + n] = (uint16_t)code0;
                        }
                        if (s1 >= thr[ci]) {
                            uint32_t n = atomicAdd(&sCnt[lr], 1u);
                            if (n < CAND_CAP) sCand[lr * CAND_CAP + n] = (uint16_t)(code0 + 1);
                        }
                        rmax[ci] = fmaxf(rmax[ci], fmaxf(s0, s1));
                    }
                }
            }
        }

        // Tighten running max across the 4 lanes sharing each row.
        #pragma unroll
        for (int i = 0; i < 4; i++) {
            float v = rmax[i];
            v = fmaxf(v, __shfl_xor_sync(0xffffffffu, v, 1));
            v = fmaxf(v, __shfl_xor_sync(0xffffffffu, v, 2));
            rmax[i] = v;
        }
    }
    __syncthreads();

    // Exact fp32 rescore: one WARP per row (lane j -> candidate j).
    for (int rr = 0; rr < 32; rr++) {
        const int lr  = wid * 32 + rr;
        const int row = blockIdx.x * 128 + lr;
        const uint32_t cnt = sCnt[lr];
        const float xx = g_xx[row];
        const float4* xr = (const float4*)(x + (size_t)row * DDIM);

        float bestv = -FLT_MAX;
        int   bestk = 0x7FFFFFFF;

        if (cnt <= CAND_CAP) {
            for (int j0 = 0; j0 < (int)cnt; j0 += 32) {
                const int j = j0 + lane;
                if (j < (int)cnt) {
                    const int k = sCand[lr * CAND_CAP + j];
                    const float4* er = (const float4*)(embed + (size_t)k * DDIM);
                    float a0 = 0.f, a1 = 0.f, a2 = 0.f, a3 = 0.f;
                    #pragma unroll 8
                    for (int i = 0; i < 32; i++) {
                        float4 xa = xr[i], ea = er[i];
                        a0 = fmaf(xa.x, ea.x, a0);
                        a1 = fmaf(xa.y, ea.y, a1);
                        a2 = fmaf(xa.z, ea.z, a2);
                        a3 = fmaf(xa.w, ea.w, a3);
                    }
                    const float dist = (-xx + 2.0f * ((a0 + a1) + (a2 + a3))) - g_ee[k];
                    if (dist > bestv || (dist == bestv && k < bestk)) { bestv = dist; bestk = k; }
                }
            }
        } else {
            for (int k = lane; k < KCODES; k += 32) {
                const float4* er = (const float4*)(embed + (size_t)k * DDIM);
                float a0 = 0.f, a1 = 0.f, a2 = 0.f, a3 = 0.f;
                #pragma unroll 8
                for (int i = 0; i < 32; i++) {
                    float4 xa = xr[i], ea = er[i];
                    a0 = fmaf(xa.x, ea.x, a0);
                    a1 = fmaf(xa.y, ea.y, a1);
                    a2 = fmaf(xa.z, ea.z, a2);
                    a3 = fmaf(xa.w, ea.w, a3);
                }
                const float dist = (-xx + 2.0f * ((a0 + a1) + (a2 + a3))) - g_ee[k];
                if (dist > bestv || (dist == bestv && k < bestk)) { bestv = dist; bestk = k; }
            }
        }

        // Warp argmax reduce; ties -> lowest index (jnp.argmax).
        #pragma unroll
        for (int o = 16; o > 0; o >>= 1) {
            const float ov = __shfl_xor_sync(0xffffffffu, bestv, o);
            const int   ok = __shfl_xor_sync(0xffffffffu, bestk, o);
            if (ov > bestv || (ov == bestv && ok < bestk)) { bestv = ov; bestk = ok; }
        }
        if (lane == 0) {
            fidx[lr] = bestk;
            g_idx[row] = bestk;
            out[IND_OFF + (size_t)row] = (float)bestk;
        }
    }
    __syncthreads();

    // quantized = embed[idx] (coalesced float4 gather-copy)
    for (int v = tid; v < 128 * 32; v += 128) {
        const int r = v >> 5, seg = v & 31;
        const float4* ep = (const float4*)(embed + (size_t)fidx[r] * DDIM);
        ((float4*)out)[(size_t)(blockIdx.x * 128 + r) * 32 + seg] = ep[seg];
    }
}

// ---------------------------------------------------------------------------
// Scatter-add: counts[idx] += 1, embed_sum[idx] += x[row]. 4 rows per block.
__global__ void k_scatter(const float* __restrict__ x) {
    int row = blockIdx.x * 4 + (threadIdx.x >> 7);
    int d   = threadIdx.x & 127;
    int idx = g_idx[row];
    atomicAdd(&g_embed_sum[(size_t)idx * DDIM + d], x[(size_t)row * DDIM + d]);
    if (d == 0) atomicAdd(&g_counts[idx], 1.0f);
}

__global__ void k_c1(const float* __restrict__ cs, float* __restrict__ out) {
    int i = threadIdx.x;  // 1024
    float ncs = cs[i] * DECAYF + OMDF * g_counts[i];
    out[NCS_OFF + (size_t)i] = ncs;
    float v = ncs;
    #pragma unroll
    for (int o = 16; o > 0; o >>= 1) v += __shfl_down_sync(0xffffffffu, v, o);
    __shared__ float s[32];
    if ((i & 31) == 0) s[i >> 5] = v;
    __syncthreads();
    if (i < 32) {
        float w = s[i];
        #pragma unroll
        for (int o = 16; o > 0; o >>= 1) w += __shfl_down_sync(0xffffffffu, w, o);
        if (i == 0) g_total = w;
    }
}

__global__ void k_c2(const float* __restrict__ ea, float* __restrict__ out) {
    int k = blockIdx.x;
    int d = threadIdx.x;  // 128
    size_t off = (size_t)k * DDIM + d;
    float nea = ea[off] * DECAYF + OMDF * g_embed_sum[off];
    out[NEA_OFF + off] = nea;
    float total = g_total;
    float ncs   = out[NCS_OFF + (size_t)k];
    float sm    = (ncs + EPSF) / (total + KEPSF) * total;
    out[EMB_OFF + off] = nea / sm;
}

// ---------------------------------------------------------------------------
extern "C" void kernel_launch(void* const* d_in, const int* in_sizes, int n_in,
                              void* d_out, int out_size) {
    const float* x  = (const float*)d_in[0];
    const float* e  = (const float*)d_in[1];
    const float* ea = (const float*)d_in[2];
    const float* cs = (const float*)d_in[3];
    float* out = (float*)d_out;

    k_init<<<KCODES, 128>>>(e);                 // launch 1
    k_packX<<<N_ROWS / 4, 256>>>(x);            // launch 2
    k_packE<<<64, 256>>>(e);                    // launch 3
    k_score<<<N_ROWS / 128, 128>>>(x, e, out);  // launch 4  (ncu capture slot)
    k_scatter<<<N_ROWS / 4, 512>>>(x);          // launch 5
    k_c1<<<1, 1024>>>(cs, out);                 // launch 6
    k_c2<<<KCODES, 128>>>(ea, out);             // launch 7
}

// round 7
// speedup vs baseline: 2.3944x; 2.0247x over previous
#include <cuda_runtime.h>
#include <cuda_bf16.h>
#include <cstdint>
#include <float.h>

// Problem constants
#define N_ROWS  (64 * 2048)   // 131072
#define DDIM    128
#define KCODES  1024

// Output layout (fp32, concatenated in reference return order)
#define Q_OFF    ((size_t)0)
#define IND_OFF  ((size_t)16777216)
#define EMB_OFF  ((size_t)16908288)
#define NCS_OFF  ((size_t)17039360)
#define NEA_OFF  ((size_t)17040384)

#define DECAYF   0.99f
#define OMDF     0.01f
#define EPSF     1e-5f
#define KEPSF    0.01024f

#define SCREEN_T 0.6f
#define CAND_CAP 64

// ---------------------------------------------------------------------------
// Scratch (__device__ globals; no allocation allowed)
__device__ float    g_counts[KCODES];
__device__ float    g_embed_sum[KCODES * DDIM];
__device__ float    g_total;
__device__ float    g_ee[KCODES];
__device__ float    g_xx[N_ROWS];
__device__ int      g_idx[N_ROWS];
__device__ uint32_t g_X16[(size_t)N_ROWS * 64];  // bf16x2-packed X rows (32 MB)
__device__ uint4    g_E16[KCODES * 16];          // bf16 E, XOR-swizzled 16B units (256 KB)

// ---------------------------------------------------------------------------
// Init: zero accumulators + per-code squared norms. Block k handles code k.
__global__ void k_init(const float* __restrict__ embed) {
    int k = blockIdx.x;       // 1024
    int t = threadIdx.x;      // 128
    g_embed_sum[(size_t)k * DDIM + t] = 0.0f;
    if (t == 0) g_counts[k] = 0.0f;
    if (k == 0 && t == 0) g_total = 0.0f;

    float v = embed[(size_t)k * DDIM + t];
    v *= v;
    __shared__ float s[4];
    #pragma unroll
    for (int o = 16; o > 0; o >>= 1) v += __shfl_down_sync(0xffffffffu, v, o);
    if ((t & 31) == 0) s[t >> 5] = v;
    __syncthreads();
    if (t == 0) g_ee[k] = s[0] + s[1] + s[2] + s[3];
}

// Pack X rows to bf16x2 + compute row squared norms. 4 rows/block, 64 thr/row.
__global__ void k_packX(const float* __restrict__ x) {
    int tid = threadIdx.x;           // 256
    int r   = blockIdx.x * 4 + (tid >> 6);
    int i   = tid & 63;
    float2 v = ((const float2*)(x + (size_t)r * DDIM))[i];
    __nv_bfloat162 b = __float22bfloat162_rn(v);
    g_X16[(size_t)r * 64 + i] = *(uint32_t*)&b;
    float ss = v.x * v.x + v.y * v.y;
    #pragma unroll
    for (int o = 16; o > 0; o >>= 1) ss += __shfl_down_sync(0xffffffffu, ss, o);
    __shared__ float s[8];
    if ((tid & 31) == 0) s[tid >> 5] = ss;
    __syncthreads();
    if ((tid & 63) == 0) g_xx[r] = s[(tid >> 5)] + s[(tid >> 5) + 1];
}

// Pack E into bf16 with per-row XOR swizzle on 16B units.
__global__ void k_packE(const float* __restrict__ embed) {
    int idx = blockIdx.x * blockDim.x + threadIdx.x;  // 16384
    int r = idx >> 4;
    int u = idx & 15;
    const float* src = embed + (size_t)r * DDIM + u * 8;
    float4 a = ((const float4*)src)[0];
    float4 b = ((const float4*)src)[1];
    __nv_bfloat162 p0 = __float22bfloat162_rn(make_float2(a.x, a.y));
    __nv_bfloat162 p1 = __float22bfloat162_rn(make_float2(a.z, a.w));
    __nv_bfloat162 p2 = __float22bfloat162_rn(make_float2(b.x, b.y));
    __nv_bfloat162 p3 = __float22bfloat162_rn(make_float2(b.z, b.w));
    uint4 out;
    out.x = *(uint32_t*)&p0; out.y = *(uint32_t*)&p1;
    out.z = *(uint32_t*)&p2; out.w = *(uint32_t*)&p3;
    g_E16[r * 16 + (u ^ (r & 7))] = out;
}

// ---------------------------------------------------------------------------
__device__ __forceinline__ uint32_t smem_u32(const void* p) {
    uint32_t a;
    asm("{ .reg .u64 t; cvta.to.shared.u64 t, %1; cvt.u32.u64 %0, t; }" : "=r"(a) : "l"(p));
    return a;
}

#define MMA_BF16(accp, af, bb0, bb1) \
    asm volatile( \
        "mma.sync.aligned.m16n8k16.row.col.f32.bf16.bf16.f32 " \
        "{%0,%1,%2,%3}, {%4,%5,%6,%7}, {%8,%9}, {%0,%1,%2,%3};" \
        : "+f"((accp)[0]), "+f"((accp)[1]), "+f"((accp)[2]), "+f"((accp)[3]) \
        : "r"((af)[0]), "r"((af)[1]), "r"((af)[2]), "r"((af)[3]), \
          "r"(bb0), "r"(bb1))

// MMA over one 16-code batch: fills acc[2][2][4]
#define BATCH_MMA(b) \
    { \
        const uint32_t rowaddr = smEa + (((b) * 16 + ctile * 8 + row8) << 8); \
        _Pragma("unroll") \
        for (int t2 = 0; t2 < 2; t2++) \
            _Pragma("unroll") \
            for (int n2 = 0; n2 < 2; n2++) \
                _Pragma("unroll") \
                for (int i = 0; i < 4; i++) acc[t2][n2][i] = 0.0f; \
        _Pragma("unroll") \
        for (int ks = 0; ks < 8; ks++) { \
            uint32_t b0, b1, b2, b3; \
            asm volatile( \
                "ldmatrix.sync.aligned.m8n8.x4.shared.b16 {%0,%1,%2,%3}, [%4];" \
                : "=r"(b0), "=r"(b1), "=r"(b2), "=r"(b3) \
                : "r"(rowaddr + (((2 * ks + khalf) ^ row8) << 4))); \
            _Pragma("unroll") \
            for (int t2 = 0; t2 < 2; t2++) { \
                MMA_BF16(acc[t2][0], afr[t2][ks], b0, b1); \
                MMA_BF16(acc[t2][1], afr[t2][ks], b2, b3); \
            } \
        } \
    }

// ---------------------------------------------------------------------------
// HMMA screening + smem-staged exact fp32 rescore.
__global__ __launch_bounds__(128, 4) void k_score(const float* __restrict__ x,
                                                  const float* __restrict__ embed,
                                                  float* __restrict__ out) {
    __shared__ __align__(16) uint4 smE[1024];       // 16 KB: E tile / rescore staging
    __shared__ float     sEE[64];
    __shared__ uint16_t  sCand[128 * CAND_CAP];     // 16 KB
    __shared__ uint32_t  sCnt[128];
    __shared__ int       fidx[128];

    const int tid  = threadIdx.x;
    const int wid  = tid >> 5;
    const int lane = tid & 31;
    const int g    = lane >> 2;
    const int tig  = lane & 3;
    const int rbase = blockIdx.x * 128 + wid * 32;

    sCnt[tid] = 0;

    // Load A fragments: 2 row-tiles x 8 k-steps x 4 regs (this warp's 32 rows).
    uint32_t afr[2][8][4];
    #pragma unroll
    for (int t2 = 0; t2 < 2; t2++) {
        const size_t rA = (size_t)(rbase + t2 * 16 + g) * 64;
        const size_t rB = rA + 8 * 64;
        #pragma unroll
        for (int ks = 0; ks < 8; ks++) {
            afr[t2][ks][0] = g_X16[rA + 8 * ks + tig];
            afr[t2][ks][1] = g_X16[rB + 8 * ks + tig];
            afr[t2][ks][2] = g_X16[rA + 8 * ks + 4 + tig];
            afr[t2][ks][3] = g_X16[rB + 8 * ks + 4 + tig];
        }
    }

    float rmax[4];
    #pragma unroll
    for (int i = 0; i < 4; i++) rmax[i] = -FLT_MAX;

    const uint32_t smEa = smem_u32(smE);
    const int row8  = lane & 7;
    const int ctile = (lane >> 4) & 1;
    const int khalf = (lane >> 3) & 1;

    for (int c = 0; c < 16; c++) {    // 16 chunks of 64 codes
        __syncthreads();
        {
            const uint4* ep = g_E16 + c * 1024;
            #pragma unroll
            for (int i = 0; i < 8; i++) smE[tid + i * 128] = ep[tid + i * 128];
            if (tid < 64) sEE[tid] = g_ee[c * 64 + tid];
        }
        __syncthreads();

        float acc[2][2][4];

        if (c == 0) {
            // Max-only warm-up pass over chunk 0 (no appends) — kills the
            // cold-threshold candidate flood.
            #pragma unroll
            for (int b = 0; b < 4; b++) {
                BATCH_MMA(b);
                #pragma unroll
                for (int n2 = 0; n2 < 2; n2++) {
                    const int le0 = b * 16 + n2 * 8 + 2 * tig;
                    const float ee0 = sEE[le0];
                    const float ee1 = sEE[le0 + 1];
                    #pragma unroll
                    for (int t2 = 0; t2 < 2; t2++)
                        #pragma unroll
                        for (int h = 0; h < 2; h++) {
                            const int ci = t2 * 2 + h;
                            const float s0 = fmaf(2.0f, acc[t2][n2][2 * h], -ee0);
                            const float s1 = fmaf(2.0f, acc[t2][n2][2 * h + 1], -ee1);
                            rmax[ci] = fmaxf(rmax[ci], fmaxf(s0, s1));
                        }
                }
            }
            #pragma unroll
            for (int i = 0; i < 4; i++) {
                float v = rmax[i];
                v = fmaxf(v, __shfl_xor_sync(0xffffffffu, v, 1));
                v = fmaxf(v, __shfl_xor_sync(0xffffffffu, v, 2));
                rmax[i] = v;
            }
        }

        #pragma unroll
        for (int b = 0; b < 4; b++) {
            BATCH_MMA(b);

            float thr[4];
            #pragma unroll
            for (int i = 0; i < 4; i++) thr[i] = rmax[i] - SCREEN_T;

            #pragma unroll
            for (int n2 = 0; n2 < 2; n2++) {
                const int le0   = b * 16 + n2 * 8 + 2 * tig;
                const int code0 = c * 64 + le0;
                const float ee0 = sEE[le0];
                const float ee1 = sEE[le0 + 1];
                #pragma unroll
                for (int t2 = 0; t2 < 2; t2++) {
                    #pragma unroll
                    for (int h = 0; h < 2; h++) {
                        const int ci = t2 * 2 + h;
                        const int lr = wid * 32 + t2 * 16 + h * 8 + g;
                        const float s0 = fmaf(2.0f, acc[t2][n2][2 * h], -ee0);
                        const float s1 = fmaf(2.0f, acc[t2][n2][2 * h + 1], -ee1);
                        if (s0 >= thr[ci]) {
                            uint32_t n = atomicAdd(&sCnt[lr], 1u);
                            if (n < CAND_CAP) sCand[lr * CAND_CAP + n] = (uint16_t)code0;
                        }
                        if (s1 >= thr[ci]) {
                            uint32_t n = atomicAdd(&sCnt[lr], 1u);
                            if (n < CAND_CAP) sCand[lr * CAND_CAP + n] = (uint16_t)(code0 + 1);
                        }
                        rmax[ci] = fmaxf(rmax[ci], fmaxf(s0, s1));
                    }
                }
            }
        }

        #pragma unroll
        for (int i = 0; i < 4; i++) {
            float v = rmax[i];
            v = fmaxf(v, __shfl_xor_sync(0xffffffffu, v, 1));
            v = fmaxf(v, __shfl_xor_sync(0xffffffffu, v, 2));
            rmax[i] = v;
        }
    }
    __syncthreads();   // sweep done; smE becomes rescore staging

    // Exact fp32 rescore: warp per row, candidates staged into smem via
    // coalesced loads. Warp w staging region: smE + w*256 (4 KB).
    // Layout (uint4, stride 33 per staged row to dodge bank conflicts):
    //   slot 0: x row (indices 0..31), slots 1..6: candidate rows.
    uint4* st = smE + wid * 256;
    for (int rr = 0; rr < 32; rr++) {
        const int lr  = wid * 32 + rr;
        const int row = blockIdx.x * 128 + lr;
        const uint32_t cnt = sCnt[lr];
        const float xx = g_xx[row];

        float bestv = -FLT_MAX;
        int   bestk = 0x7FFFFFFF;

        if (cnt <= CAND_CAP) {
            st[lane] = ((const uint4*)(x + (size_t)row * DDIM))[lane];
            __syncwarp();
            for (int b0 = 0; b0 < (int)cnt; b0 += 6) {
                const int m = min(6, (int)cnt - b0);
                int kj = 0;
                if (lane < m) kj = sCand[lr * CAND_CAP + b0 + lane];
                for (int j = 0; j < m; j++) {
                    const int kk = __shfl_sync(0xffffffffu, kj, j);
                    st[(1 + j) * 33 + lane] =
                        ((const uint4*)(embed + (size_t)kk * DDIM))[lane];
                }
                __syncwarp();
                if (lane < m) {
                    const uint4* er = st + (1 + lane) * 33;
                    float a0 = 0.f, a1 = 0.f, a2 = 0.f, a3 = 0.f;
                    #pragma unroll 8
                    for (int i = 0; i < 32; i++) {
                        float4 xa = *(const float4*)&st[i];
                        float4 ea = *(const float4*)&er[i];
                        a0 = fmaf(xa.x, ea.x, a0);
                        a1 = fmaf(xa.y, ea.y, a1);
                        a2 = fmaf(xa.z, ea.z, a2);
                        a3 = fmaf(xa.w, ea.w, a3);
                    }
                    const float dist = (-xx + 2.0f * ((a0 + a1) + (a2 + a3))) - g_ee[kj];
                    if (dist > bestv || (dist == bestv && kj < bestk)) {
                        bestv = dist; bestk = kj;
                    }
                }
                __syncwarp();
            }
        } else {
            // Rare overflow: exact full scan, lane-strided.
            const float4* xr = (const float4*)(x + (size_t)row * DDIM);
            for (int k = lane; k < KCODES; k += 32) {
                const float4* er = (const float4*)(embed + (size_t)k * DDIM);
                float a0 = 0.f, a1 = 0.f, a2 = 0.f, a3 = 0.f;
                #pragma unroll 8
                for (int i = 0; i < 32; i++) {
                    float4 xa = xr[i], ea = er[i];
                    a0 = fmaf(xa.x, ea.x, a0);
                    a1 = fmaf(xa.y, ea.y, a1);
                    a2 = fmaf(xa.z, ea.z, a2);
                    a3 = fmaf(xa.w, ea.w, a3);
                }
                const float dist = (-xx + 2.0f * ((a0 + a1) + (a2 + a3))) - g_ee[k];
                if (dist > bestv || (dist == bestv && k < bestk)) { bestv = dist; bestk = k; }
            }
        }

        // Warp argmax reduce; ties -> lowest index (jnp.argmax).
        #pragma unroll
        for (int o = 16; o > 0; o >>= 1) {
            const float ov = __shfl_xor_sync(0xffffffffu, bestv, o);
            const int   ok = __shfl_xor_sync(0xffffffffu, bestk, o);
            if (ov > bestv || (ov == bestv && ok < bestk)) { bestv = ov; bestk = ok; }
        }
        if (lane == 0) {
            fidx[lr] = bestk;
            g_idx[row] = bestk;
            out[IND_OFF + (size_t)row] = (float)bestk;
        }
    }
    __syncthreads();

    // quantized = embed[idx] (coalesced float4 gather-copy)
    for (int v = tid; v < 128 * 32; v += 128) {
        const int r = v >> 5, seg = v & 31;
        const float4* ep = (const float4*)(embed + (size_t)fidx[r] * DDIM);
        ((float4*)out)[(size_t)(blockIdx.x * 128 + r) * 32 + seg] = ep[seg];
    }
}

// ---------------------------------------------------------------------------
// Scatter-add via vector RED: 8 rows/block, 32 lanes x 4 dims per row.
__global__ void k_scatter(const float* __restrict__ x) {
    const int row = blockIdx.x * 8 + (threadIdx.x >> 5);
    const int d4  = (threadIdx.x & 31) * 4;
    const int idx = g_idx[row];
    const float4 v = *(const float4*)(x + (size_t)row * DDIM + d4);
    float* dst = &g_embed_sum[(size_t)idx * DDIM + d4];
    asm volatile("red.global.add.v4.f32 [%0], {%1,%2,%3,%4};"
                 :: "l"(dst), "f"(v.x), "f"(v.y), "f"(v.z), "f"(v.w)
                 : "memory");
    if (d4 == 0) atomicAdd(&g_counts[idx], 1.0f);
}

__global__ void k_c1(const float* __restrict__ cs, float* __restrict__ out) {
    int i = threadIdx.x;  // 1024
    float ncs = cs[i] * DECAYF + OMDF * g_counts[i];
    out[NCS_OFF + (size_t)i] = ncs;
    float v = ncs;
    #pragma unroll
    for (int o = 16; o > 0; o >>= 1) v += __shfl_down_sync(0xffffffffu, v, o);
    __shared__ float s[32];
    if ((i & 31) == 0) s[i >> 5] = v;
    __syncthreads();
    if (i < 32) {
        float w = s[i];
        #pragma unroll
        for (int o = 16; o > 0; o >>= 1) w += __shfl_down_sync(0xffffffffu, w, o);
        if (i == 0) g_total = w;
    }
}

__global__ void k_c2(const float* __restrict__ ea, float* __restrict__ out) {
    int k = blockIdx.x;
    int d = threadIdx.x;  // 128
    size_t off = (size_t)k * DDIM + d;
    float nea = ea[off] * DECAYF + OMDF * g_embed_sum[off];
    out[NEA_OFF + off] = nea;
    float total = g_total;
    float ncs   = out[NCS_OFF + (size_t)k];
    float sm    = (ncs + EPSF) / (total + KEPSF) * total;
    out[EMB_OFF + off] = nea / sm;
}

// ---------------------------------------------------------------------------
extern "C" void kernel_launch(void* const* d_in, const int* in_sizes, int n_in,
                              void* d_out, int out_size) {
    const float* x  = (const float*)d_in[0];
    const float* e  = (const float*)d_in[1];
    const float* ea = (const float*)d_in[2];
    const float* cs = (const float*)d_in[3];
    float* out = (float*)d_out;

    k_init<<<KCODES, 128>>>(e);                 // launch 1
    k_packX<<<N_ROWS / 4, 256>>>(x);            // launch 2
    k_packE<<<64, 256>>>(e);                    // launch 3
    k_score<<<N_ROWS / 128, 128>>>(x, e, out);  // launch 4  (ncu capture slot)
    k_scatter<<<N_ROWS / 8, 256>>>(x);          // launch 5
    k_c1<<<1, 1024>>>(cs, out);                 // launch 6
    k_c2<<<KCODES, 128>>>(ea, out);             // launch 7
}

// round 8
// speedup vs baseline: 2.4052x; 1.0045x over previous
#include <cuda_runtime.h>
#include <cuda_bf16.h>
#include <cstdint>
#include <float.h>

// Problem constants
#define N_ROWS  (64 * 2048)   // 131072
#define DDIM    128
#define KCODES  1024

// Output layout (fp32, concatenated in reference return order)
#define Q_OFF    ((size_t)0)
#define IND_OFF  ((size_t)16777216)
#define EMB_OFF  ((size_t)16908288)
#define NCS_OFF  ((size_t)17039360)
#define NEA_OFF  ((size_t)17040384)

#define DECAYF   0.99f
#define OMDF     0.01f
#define EPSF     1e-5f
#define KEPSF    0.01024f

#define SCREEN_T 0.6f
#define CAND_CAP 64

// ---------------------------------------------------------------------------
// Scratch (__device__ globals; no allocation allowed)
__device__ float    g_counts[KCODES];
__device__ float    g_embed_sum[KCODES * DDIM];
__device__ float    g_total;
__device__ float    g_ee[KCODES];
__device__ float    g_xx[N_ROWS];
__device__ int      g_idx[N_ROWS];
__device__ uint32_t g_X16[(size_t)N_ROWS * 64];  // bf16x2-packed X rows (32 MB)
__device__ uint4    g_E16[KCODES * 16];          // bf16 E, XOR-swizzled 16B units (256 KB)

// ---------------------------------------------------------------------------
// Init: zero accumulators + per-code squared norms. Block k handles code k.
__global__ void k_init(const float* __restrict__ embed) {
    int k = blockIdx.x;       // 1024
    int t = threadIdx.x;      // 128
    g_embed_sum[(size_t)k * DDIM + t] = 0.0f;
    if (t == 0) g_counts[k] = 0.0f;
    if (k == 0 && t == 0) g_total = 0.0f;

    float v = embed[(size_t)k * DDIM + t];
    v *= v;
    __shared__ float s[4];
    #pragma unroll
    for (int o = 16; o > 0; o >>= 1) v += __shfl_down_sync(0xffffffffu, v, o);
    if ((t & 31) == 0) s[t >> 5] = v;
    __syncthreads();
    if (t == 0) g_ee[k] = s[0] + s[1] + s[2] + s[3];
}

// Pack X rows to bf16x2 + compute row squared norms. 4 rows/block, 64 thr/row.
__global__ void k_packX(const float* __restrict__ x) {
    int tid = threadIdx.x;           // 256
    int r   = blockIdx.x * 4 + (tid >> 6);
    int i   = tid & 63;
    float2 v = ((const float2*)(x + (size_t)r * DDIM))[i];
    __nv_bfloat162 b = __float22bfloat162_rn(v);
    g_X16[(size_t)r * 64 + i] = *(uint32_t*)&b;
    float ss = v.x * v.x + v.y * v.y;
    #pragma unroll
    for (int o = 16; o > 0; o >>= 1) ss += __shfl_down_sync(0xffffffffu, ss, o);
    __shared__ float s[8];
    if ((tid & 31) == 0) s[tid >> 5] = ss;
    __syncthreads();
    if ((tid & 63) == 0) g_xx[r] = s[(tid >> 5)] + s[(tid >> 5) + 1];
}

// Pack E into bf16 with per-row XOR swizzle on 16B units.
__global__ void k_packE(const float* __restrict__ embed) {
    int idx = blockIdx.x * blockDim.x + threadIdx.x;  // 16384
    int r = idx >> 4;
    int u = idx & 15;
    const float* src = embed + (size_t)r * DDIM + u * 8;
    float4 a = ((const float4*)src)[0];
    float4 b = ((const float4*)src)[1];
    __nv_bfloat162 p0 = __float22bfloat162_rn(make_float2(a.x, a.y));
    __nv_bfloat162 p1 = __float22bfloat162_rn(make_float2(a.z, a.w));
    __nv_bfloat162 p2 = __float22bfloat162_rn(make_float2(b.x, b.y));
    __nv_bfloat162 p3 = __float22bfloat162_rn(make_float2(b.z, b.w));
    uint4 out;
    out.x = *(uint32_t*)&p0; out.y = *(uint32_t*)&p1;
    out.z = *(uint32_t*)&p2; out.w = *(uint32_t*)&p3;
    g_E16[r * 16 + (u ^ (r & 7))] = out;
}

// ---------------------------------------------------------------------------
__device__ __forceinline__ uint32_t smem_u32(const void* p) {
    uint32_t a;
    asm("{ .reg .u64 t; cvta.to.shared.u64 t, %1; cvt.u32.u64 %0, t; }" : "=r"(a) : "l"(p));
    return a;
}

#define MMA_BF16(accp, af, bb0, bb1) \
    asm volatile( \
        "mma.sync.aligned.m16n8k16.row.col.f32.bf16.bf16.f32 " \
        "{%0,%1,%2,%3}, {%4,%5,%6,%7}, {%8,%9}, {%0,%1,%2,%3};" \
        : "+f"((accp)[0]), "+f"((accp)[1]), "+f"((accp)[2]), "+f"((accp)[3]) \
        : "r"((af)[0]), "r"((af)[1]), "r"((af)[2]), "r"((af)[3]), \
          "r"(bb0), "r"(bb1))

// MMA over one 16-code batch (1 m-tile of 16 rows): fills acc[2][4]
#define BATCH_MMA(b) \
    { \
        const uint32_t rowaddr = smEa + (((b) * 16 + ctile * 8 + row8) << 8); \
        _Pragma("unroll") \
        for (int n2 = 0; n2 < 2; n2++) \
            _Pragma("unroll") \
            for (int i = 0; i < 4; i++) acc[n2][i] = 0.0f; \
        _Pragma("unroll") \
        for (int ks = 0; ks < 8; ks++) { \
            uint32_t b0, b1, b2, b3; \
            asm volatile( \
                "ldmatrix.sync.aligned.m8n8.x4.shared.b16 {%0,%1,%2,%3}, [%4];" \
                : "=r"(b0), "=r"(b1), "=r"(b2), "=r"(b3) \
                : "r"(rowaddr + (((2 * ks + khalf) ^ row8) << 4))); \
            MMA_BF16(acc[0], afr[ks], b0, b1); \
            MMA_BF16(acc[1], afr[ks], b2, b3); \
        } \
    }

// ---------------------------------------------------------------------------
// HMMA screening + smem-staged exact fp32 rescore.
// CTA = 128 threads (4 warps), each warp owns 16 rows -> CTA covers 64 rows.
__global__ __launch_bounds__(128, 6) void k_score(const float* __restrict__ x,
                                                  const float* __restrict__ embed,
                                                  float* __restrict__ out) {
    __shared__ __align__(16) uint4 smE[1024];       // 16 KB: E tile / rescore staging
    __shared__ float     sEE[64];
    __shared__ uint16_t  sCand[64 * CAND_CAP];      // 8 KB
    __shared__ uint32_t  sCnt[64];
    __shared__ int       fidx[64];

    const int tid  = threadIdx.x;
    const int wid  = tid >> 5;
    const int lane = tid & 31;
    const int g    = lane >> 2;
    const int tig  = lane & 3;
    const int rbase = blockIdx.x * 64 + wid * 16;

    if (tid < 64) sCnt[tid] = 0;

    // Load A fragments: 8 k-steps x 4 regs (this warp's 16 rows).
    uint32_t afr[8][4];
    {
        const size_t rA = (size_t)(rbase + g) * 64;
        const size_t rB = rA + 8 * 64;
        #pragma unroll
        for (int ks = 0; ks < 8; ks++) {
            afr[ks][0] = g_X16[rA + 8 * ks + tig];
            afr[ks][1] = g_X16[rB + 8 * ks + tig];
            afr[ks][2] = g_X16[rA + 8 * ks + 4 + tig];
            afr[ks][3] = g_X16[rB + 8 * ks + 4 + tig];
        }
    }

    float rmax[2];
    rmax[0] = -FLT_MAX; rmax[1] = -FLT_MAX;

    const uint32_t smEa = smem_u32(smE);
    const int row8  = lane & 7;
    const int ctile = (lane >> 4) & 1;
    const int khalf = (lane >> 3) & 1;

    for (int c = 0; c < 16; c++) {    // 16 chunks of 64 codes
        __syncthreads();
        {
            const uint4* ep = g_E16 + c * 1024;
            #pragma unroll
            for (int i = 0; i < 8; i++) smE[tid + i * 128] = ep[tid + i * 128];
            if (tid < 64) sEE[tid] = g_ee[c * 64 + tid];
        }
        __syncthreads();

        float acc[2][4];

        if (c == 0) {
            // Max-only warm-up pass over chunk 0 (no appends) — kills the
            // cold-threshold candidate flood.
            #pragma unroll
            for (int b = 0; b < 4; b++) {
                BATCH_MMA(b);
                #pragma unroll
                for (int n2 = 0; n2 < 2; n2++) {
                    const int le0 = b * 16 + n2 * 8 + 2 * tig;
                    const float ee0 = sEE[le0];
                    const float ee1 = sEE[le0 + 1];
                    rmax[0] = fmaxf(rmax[0],
                                    fmaxf(fmaf(2.0f, acc[n2][0], -ee0),
                                          fmaf(2.0f, acc[n2][1], -ee1)));
                    rmax[1] = fmaxf(rmax[1],
                                    fmaxf(fmaf(2.0f, acc[n2][2], -ee0),
                                          fmaf(2.0f, acc[n2][3], -ee1)));
                }
            }
            #pragma unroll
            for (int i = 0; i < 2; i++) {
                float v = rmax[i];
                v = fmaxf(v, __shfl_xor_sync(0xffffffffu, v, 1));
                v = fmaxf(v, __shfl_xor_sync(0xffffffffu, v, 2));
                rmax[i] = v;
            }
        }

        #pragma unroll
        for (int b = 0; b < 4; b++) {
            BATCH_MMA(b);

            const float thr0 = rmax[0] - SCREEN_T;
            const float thr1 = rmax[1] - SCREEN_T;
            const int lr0 = wid * 16 + g;
            const int lr1 = lr0 + 8;

            #pragma unroll
            for (int n2 = 0; n2 < 2; n2++) {
                const int le0   = b * 16 + n2 * 8 + 2 * tig;
                const int code0 = c * 64 + le0;
                const float ee0 = sEE[le0];
                const float ee1 = sEE[le0 + 1];

                const float s0 = fmaf(2.0f, acc[n2][0], -ee0);   // row g
                const float s1 = fmaf(2.0f, acc[n2][1], -ee1);   // row g
                const float s2 = fmaf(2.0f, acc[n2][2], -ee0);   // row g+8
                const float s3 = fmaf(2.0f, acc[n2][3], -ee1);   // row g+8

                if (s0 >= thr0) {
                    uint32_t n = atomicAdd(&sCnt[lr0], 1u);
                    if (n < CAND_CAP) sCand[lr0 * CAND_CAP + n] = (uint16_t)code0;
                }
                if (s1 >= thr0) {
                    uint32_t n = atomicAdd(&sCnt[lr0], 1u);
                    if (n < CAND_CAP) sCand[lr0 * CAND_CAP + n] = (uint16_t)(code0 + 1);
                }
                if (s2 >= thr1) {
                    uint32_t n = atomicAdd(&sCnt[lr1], 1u);
                    if (n < CAND_CAP) sCand[lr1 * CAND_CAP + n] = (uint16_t)code0;
                }
                if (s3 >= thr1) {
                    uint32_t n = atomicAdd(&sCnt[lr1], 1u);
                    if (n < CAND_CAP) sCand[lr1 * CAND_CAP + n] = (uint16_t)(code0 + 1);
                }
                rmax[0] = fmaxf(rmax[0], fmaxf(s0, s1));
                rmax[1] = fmaxf(rmax[1], fmaxf(s2, s3));
            }
        }

        #pragma unroll
        for (int i = 0; i < 2; i++) {
            float v = rmax[i];
            v = fmaxf(v, __shfl_xor_sync(0xffffffffu, v, 1));
            v = fmaxf(v, __shfl_xor_sync(0xffffffffu, v, 2));
            rmax[i] = v;
        }
    }
    __syncthreads();   // sweep done; smE becomes rescore staging

    // Exact fp32 rescore: warp per row, candidates staged into smem via
    // coalesced loads. Warp w staging region: smE + w*256 (4 KB).
    // Layout (uint4, stride 33 per staged row to dodge bank conflicts):
    //   slot 0: x row (indices 0..31), slots 1..6: candidate rows.
    uint4* st = smE + wid * 256;
    for (int rr = 0; rr < 16; rr++) {
        const int lr  = wid * 16 + rr;
        const int row = blockIdx.x * 64 + lr;
        const uint32_t cnt = sCnt[lr];
        const float xx = g_xx[row];

        float bestv = -FLT_MAX;
        int   bestk = 0x7FFFFFFF;

        if (cnt <= CAND_CAP) {
            st[lane] = ((const uint4*)(x + (size_t)row * DDIM))[lane];
            __syncwarp();
            for (int b0 = 0; b0 < (int)cnt; b0 += 6) {
                const int m = min(6, (int)cnt - b0);
                int kj = 0;
                if (lane < m) kj = sCand[lr * CAND_CAP + b0 + lane];
                for (int j = 0; j < m; j++) {
                    const int kk = __shfl_sync(0xffffffffu, kj, j);
                    st[(1 + j) * 33 + lane] =
                        ((const uint4*)(embed + (size_t)kk * DDIM))[lane];
                }
                __syncwarp();
                if (lane < m) {
                    const uint4* er = st + (1 + lane) * 33;
                    float a0 = 0.f, a1 = 0.f, a2 = 0.f, a3 = 0.f;
                    #pragma unroll 8
                    for (int i = 0; i < 32; i++) {
                        float4 xa = *(const float4*)&st[i];
                        float4 ea = *(const float4*)&er[i];
                        a0 = fmaf(xa.x, ea.x, a0);
                        a1 = fmaf(xa.y, ea.y, a1);
                        a2 = fmaf(xa.z, ea.z, a2);
                        a3 = fmaf(xa.w, ea.w, a3);
                    }
                    const float dist = (-xx + 2.0f * ((a0 + a1) + (a2 + a3))) - g_ee[kj];
                    if (dist > bestv || (dist == bestv && kj < bestk)) {
                        bestv = dist; bestk = kj;
                    }
                }
                __syncwarp();
            }
        } else {
            // Rare overflow: exact full scan, lane-strided.
            const float4* xr = (const float4*)(x + (size_t)row * DDIM);
            for (int k = lane; k < KCODES; k += 32) {
                const float4* er = (const float4*)(embed + (size_t)k * DDIM);
                float a0 = 0.f, a1 = 0.f, a2 = 0.f, a3 = 0.f;
                #pragma unroll 8
                for (int i = 0; i < 32; i++) {
                    float4 xa = xr[i], ea = er[i];
                    a0 = fmaf(xa.x, ea.x, a0);
                    a1 = fmaf(xa.y, ea.y, a1);
                    a2 = fmaf(xa.z, ea.z, a2);
                    a3 = fmaf(xa.w, ea.w, a3);
                }
                const float dist = (-xx + 2.0f * ((a0 + a1) + (a2 + a3))) - g_ee[k];
                if (dist > bestv || (dist == bestv && k < bestk)) { bestv = dist; bestk = k; }
            }
        }

        // Warp argmax reduce; ties -> lowest index (jnp.argmax).
        #pragma unroll
        for (int o = 16; o > 0; o >>= 1) {
            const float ov = __shfl_xor_sync(0xffffffffu, bestv, o);
            const int   ok = __shfl_xor_sync(0xffffffffu, bestk, o);
            if (ov > bestv || (ov == bestv && ok < bestk)) { bestv = ov; bestk = ok; }
        }
        if (lane == 0) {
            fidx[lr] = bestk;
            g_idx[row] = bestk;
            out[IND_OFF + (size_t)row] = (float)bestk;
        }
    }
    __syncthreads();

    // quantized = embed[idx] (coalesced float4 gather-copy)
    for (int v = tid; v < 64 * 32; v += 128) {
        const int r = v >> 5, seg = v & 31;
        const float4* ep = (const float4*)(embed + (size_t)fidx[r] * DDIM);
        ((float4*)out)[(size_t)(blockIdx.x * 64 + r) * 32 + seg] = ep[seg];
    }
}

// ---------------------------------------------------------------------------
// Scatter-add via vector RED: 8 rows/block, 32 lanes x 4 dims per row.
__global__ void k_scatter(const float* __restrict__ x) {
    const int row = blockIdx.x * 8 + (threadIdx.x >> 5);
    const int d4  = (threadIdx.x & 31) * 4;
    const int idx = g_idx[row];
    const float4 v = *(const float4*)(x + (size_t)row * DDIM + d4);
    float* dst = &g_embed_sum[(size_t)idx * DDIM + d4];
    asm volatile("red.global.add.v4.f32 [%0], {%1,%2,%3,%4};"
                 :: "l"(dst), "f"(v.x), "f"(v.y), "f"(v.z), "f"(v.w)
                 : "memory");
    if (d4 == 0) atomicAdd(&g_counts[idx], 1.0f);
}

__global__ void k_c1(const float* __restrict__ cs, float* __restrict__ out) {
    int i = threadIdx.x;  // 1024
    float ncs = cs[i] * DECAYF + OMDF * g_counts[i];
    out[NCS_OFF + (size_t)i] = ncs;
    float v = ncs;
    #pragma unroll
    for (int o = 16; o > 0; o >>= 1) v += __shfl_down_sync(0xffffffffu, v, o);
    __shared__ float s[32];
    if ((i & 31) == 0) s[i >> 5] = v;
    __syncthreads();
    if (i < 32) {
        float w = s[i];
        #pragma unroll
        for (int o = 16; o > 0; o >>= 1) w += __shfl_down_sync(0xffffffffu, w, o);
        if (i == 0) g_total = w;
    }
}

__global__ void k_c2(const float* __restrict__ ea, float* __restrict__ out) {
    int k = blockIdx.x;
    int d = threadIdx.x;  // 128
    size_t off = (size_t)k * DDIM + d;
    float nea = ea[off] * DECAYF + OMDF * g_embed_sum[off];
    out[NEA_OFF + off] = nea;
    float total = g_total;
    float ncs   = out[NCS_OFF + (size_t)k];
    float sm    = (ncs + EPSF) / (total + KEPSF) * total;
    out[EMB_OFF + off] = nea / sm;
}

// ---------------------------------------------------------------------------
extern "C" void kernel_launch(void* const* d_in, const int* in_sizes, int n_in,
                              void* d_out, int out_size) {
    const float* x  = (const float*)d_in[0];
    const float* e  = (const float*)d_in[1];
    const float* ea = (const float*)d_in[2];
    const float* cs = (const float*)d_in[3];
    float* out = (float*)d_out;

    k_init<<<KCODES, 128>>>(e);                 // launch 1
    k_packX<<<N_ROWS / 4, 256>>>(x);            // launch 2
    k_packE<<<64, 256>>>(e);                    // launch 3
    k_score<<<N_ROWS / 64, 128>>>(x, e, out);   // launch 4  (ncu capture slot)
    k_scatter<<<N_ROWS / 8, 256>>>(x);          // launch 5
    k_c1<<<1, 1024>>>(cs, out);                 // launch 6
    k_c2<<<KCODES, 128>>>(ea, out);             // launch 7
}

// round 9
// speedup vs baseline: 3.1465x; 1.3082x over previous
#include <cuda_runtime.h>
#include <cuda_bf16.h>
#include <cstdint>
#include <float.h>

// Problem constants
#define N_ROWS  (64 * 2048)   // 131072
#define DDIM    128
#define KCODES  1024

// Output layout (fp32, concatenated in reference return order)
#define Q_OFF    ((size_t)0)
#define IND_OFF  ((size_t)16777216)
#define EMB_OFF  ((size_t)16908288)
#define NCS_OFF  ((size_t)17039360)
#define NEA_OFF  ((size_t)17040384)

#define DECAYF   0.99f
#define OMDF     0.01f
#define EPSF     1e-5f
#define KEPSF    0.01024f

#define SCREEN_T 0.6f
#define CAND_CAP 64

// ---------------------------------------------------------------------------
// Scratch (__device__ globals; no allocation allowed)
__device__ float    g_counts[KCODES];
__device__ float    g_embed_sum[KCODES * DDIM];
__device__ float    g_total;
__device__ float    g_ee[KCODES];
__device__ float    g_xx[N_ROWS];
__device__ int      g_idx[N_ROWS];
__device__ uint32_t g_X16[(size_t)N_ROWS * 64];  // bf16x2-packed X rows (32 MB)
__device__ uint4    g_E16[KCODES * 16];          // bf16 E, XOR-swizzled 16B units (256 KB)

// ---------------------------------------------------------------------------
// Init: zero accumulators + per-code squared norms + pack E (bf16, swizzled).
// Block k handles code k.
__global__ void k_init(const float* __restrict__ embed) {
    int k = blockIdx.x;       // 1024
    int t = threadIdx.x;      // 128
    g_embed_sum[(size_t)k * DDIM + t] = 0.0f;
    if (t == 0) g_counts[k] = 0.0f;
    if (k == 0 && t == 0) g_total = 0.0f;

    float v = embed[(size_t)k * DDIM + t];
    v *= v;
    __shared__ float s[4];
    #pragma unroll
    for (int o = 16; o > 0; o >>= 1) v += __shfl_down_sync(0xffffffffu, v, o);
    if ((t & 31) == 0) s[t >> 5] = v;
    __syncthreads();
    if (t == 0) g_ee[k] = s[0] + s[1] + s[2] + s[3];

    // Pack this code's row into bf16 with per-row XOR swizzle on 16B units.
    if (t < 16) {
        const float* src = embed + (size_t)k * DDIM + t * 8;
        float4 a = ((const float4*)src)[0];
        float4 b = ((const float4*)src)[1];
        __nv_bfloat162 p0 = __float22bfloat162_rn(make_float2(a.x, a.y));
        __nv_bfloat162 p1 = __float22bfloat162_rn(make_float2(a.z, a.w));
        __nv_bfloat162 p2 = __float22bfloat162_rn(make_float2(b.x, b.y));
        __nv_bfloat162 p3 = __float22bfloat162_rn(make_float2(b.z, b.w));
        uint4 o4;
        o4.x = *(uint32_t*)&p0; o4.y = *(uint32_t*)&p1;
        o4.z = *(uint32_t*)&p2; o4.w = *(uint32_t*)&p3;
        g_E16[k * 16 + (t ^ (k & 7))] = o4;
    }
}

// Pack X rows to bf16x2 + compute row squared norms. 4 rows/block, 64 thr/row.
__global__ void k_packX(const float* __restrict__ x) {
    int tid = threadIdx.x;           // 256
    int r   = blockIdx.x * 4 + (tid >> 6);
    int i   = tid & 63;
    float2 v = ((const float2*)(x + (size_t)r * DDIM))[i];
    __nv_bfloat162 b = __float22bfloat162_rn(v);
    g_X16[(size_t)r * 64 + i] = *(uint32_t*)&b;
    float ss = v.x * v.x + v.y * v.y;
    #pragma unroll
    for (int o = 16; o > 0; o >>= 1) ss += __shfl_down_sync(0xffffffffu, ss, o);
    __shared__ float s[8];
    if ((tid & 31) == 0) s[tid >> 5] = ss;
    __syncthreads();
    if ((tid & 63) == 0) g_xx[r] = s[(tid >> 5)] + s[(tid >> 5) + 1];
}

// ---------------------------------------------------------------------------
__device__ __forceinline__ uint32_t smem_u32(const void* p) {
    uint32_t a;
    asm("{ .reg .u64 t; cvta.to.shared.u64 t, %1; cvt.u32.u64 %0, t; }" : "=r"(a) : "l"(p));
    return a;
}

#define MMA_BF16(accp, af, bb0, bb1) \
    asm volatile( \
        "mma.sync.aligned.m16n8k16.row.col.f32.bf16.bf16.f32 " \
        "{%0,%1,%2,%3}, {%4,%5,%6,%7}, {%8,%9}, {%0,%1,%2,%3};" \
        : "+f"((accp)[0]), "+f"((accp)[1]), "+f"((accp)[2]), "+f"((accp)[3]) \
        : "r"((af)[0]), "r"((af)[1]), "r"((af)[2]), "r"((af)[3]), \
          "r"(bb0), "r"(bb1))

// MMA over one 16-code batch (1 m-tile of 16 rows): fills acc[2][4]
#define BATCH_MMA(b) \
    { \
        const uint32_t rowaddr = smEa + (((b) * 16 + ctile * 8 + row8) << 8); \
        _Pragma("unroll") \
        for (int n2 = 0; n2 < 2; n2++) \
            _Pragma("unroll") \
            for (int i = 0; i < 4; i++) acc[n2][i] = 0.0f; \
        _Pragma("unroll") \
        for (int ks = 0; ks < 8; ks++) { \
            uint32_t b0, b1, b2, b3; \
            asm volatile( \
                "ldmatrix.sync.aligned.m8n8.x4.shared.b16 {%0,%1,%2,%3}, [%4];" \
                : "=r"(b0), "=r"(b1), "=r"(b2), "=r"(b3) \
                : "r"(rowaddr + (((2 * ks + khalf) ^ row8) << 4))); \
            MMA_BF16(acc[0], afr[ks], b0, b1); \
            MMA_BF16(acc[1], afr[ks], b2, b3); \
        } \
    }

// ---------------------------------------------------------------------------
// HMMA screening + quad-cooperative exact fp32 rescore.
// CTA = 128 threads (4 warps), each warp owns 16 rows -> CTA covers 64 rows.
__global__ __launch_bounds__(128, 6) void k_score(const float* __restrict__ x,
                                                  const float* __restrict__ embed,
                                                  float* __restrict__ out) {
    __shared__ __align__(16) uint4 smE[1024];       // 16 KB: E tile
    __shared__ float     sEE[64];
    __shared__ uint16_t  sCand[64 * CAND_CAP];      // 8 KB
    __shared__ uint32_t  sCnt[64];
    __shared__ int       fidx[64];

    const int tid  = threadIdx.x;
    const int wid  = tid >> 5;
    const int lane = tid & 31;
    const int g    = lane >> 2;
    const int tig  = lane & 3;
    const int rbase = blockIdx.x * 64 + wid * 16;

    if (tid < 64) sCnt[tid] = 0;

    // Load A fragments: 8 k-steps x 4 regs (this warp's 16 rows).
    uint32_t afr[8][4];
    {
        const size_t rA = (size_t)(rbase + g) * 64;
        const size_t rB = rA + 8 * 64;
        #pragma unroll
        for (int ks = 0; ks < 8; ks++) {
            afr[ks][0] = g_X16[rA + 8 * ks + tig];
            afr[ks][1] = g_X16[rB + 8 * ks + tig];
            afr[ks][2] = g_X16[rA + 8 * ks + 4 + tig];
            afr[ks][3] = g_X16[rB + 8 * ks + 4 + tig];
        }
    }

    float rmax[2];
    rmax[0] = -FLT_MAX; rmax[1] = -FLT_MAX;

    const uint32_t smEa = smem_u32(smE);
    const int row8  = lane & 7;
    const int ctile = (lane >> 4) & 1;
    const int khalf = (lane >> 3) & 1;

    for (int c = 0; c < 16; c++) {    // 16 chunks of 64 codes
        __syncthreads();
        {
            const uint4* ep = g_E16 + c * 1024;
            #pragma unroll
            for (int i = 0; i < 8; i++) smE[tid + i * 128] = ep[tid + i * 128];
            if (tid < 64) sEE[tid] = g_ee[c * 64 + tid];
        }
        __syncthreads();

        float acc[2][4];

        if (c == 0) {
            // Max-only warm-up pass over chunk 0 (no appends).
            #pragma unroll
            for (int b = 0; b < 4; b++) {
                BATCH_MMA(b);
                #pragma unroll
                for (int n2 = 0; n2 < 2; n2++) {
                    const int le0 = b * 16 + n2 * 8 + 2 * tig;
                    const float ee0 = sEE[le0];
                    const float ee1 = sEE[le0 + 1];
                    rmax[0] = fmaxf(rmax[0],
                                    fmaxf(fmaf(2.0f, acc[n2][0], -ee0),
                                          fmaf(2.0f, acc[n2][1], -ee1)));
                    rmax[1] = fmaxf(rmax[1],
                                    fmaxf(fmaf(2.0f, acc[n2][2], -ee0),
                                          fmaf(2.0f, acc[n2][3], -ee1)));
                }
            }
            #pragma unroll
            for (int i = 0; i < 2; i++) {
                float v = rmax[i];
                v = fmaxf(v, __shfl_xor_sync(0xffffffffu, v, 1));
                v = fmaxf(v, __shfl_xor_sync(0xffffffffu, v, 2));
                rmax[i] = v;
            }
        }

        #pragma unroll
        for (int b = 0; b < 4; b++) {
            BATCH_MMA(b);

            const float thr0 = rmax[0] - SCREEN_T;
            const float thr1 = rmax[1] - SCREEN_T;
            const int lr0 = wid * 16 + g;
            const int lr1 = lr0 + 8;

            #pragma unroll
            for (int n2 = 0; n2 < 2; n2++) {
                const int le0   = b * 16 + n2 * 8 + 2 * tig;
                const int code0 = c * 64 + le0;
                const float ee0 = sEE[le0];
                const float ee1 = sEE[le0 + 1];

                const float s0 = fmaf(2.0f, acc[n2][0], -ee0);   // row g
                const float s1 = fmaf(2.0f, acc[n2][1], -ee1);   // row g
                const float s2 = fmaf(2.0f, acc[n2][2], -ee0);   // row g+8
                const float s3 = fmaf(2.0f, acc[n2][3], -ee1);   // row g+8

                if (s0 >= thr0) {
                    uint32_t n = atomicAdd(&sCnt[lr0], 1u);
                    if (n < CAND_CAP) sCand[lr0 * CAND_CAP + n] = (uint16_t)code0;
                }
                if (s1 >= thr0) {
                    uint32_t n = atomicAdd(&sCnt[lr0], 1u);
                    if (n < CAND_CAP) sCand[lr0 * CAND_CAP + n] = (uint16_t)(code0 + 1);
                }
                if (s2 >= thr1) {
                    uint32_t n = atomicAdd(&sCnt[lr1], 1u);
                    if (n < CAND_CAP) sCand[lr1 * CAND_CAP + n] = (uint16_t)code0;
                }
                if (s3 >= thr1) {
                    uint32_t n = atomicAdd(&sCnt[lr1], 1u);
                    if (n < CAND_CAP) sCand[lr1 * CAND_CAP + n] = (uint16_t)(code0 + 1);
                }
                rmax[0] = fmaxf(rmax[0], fmaxf(s0, s1));
                rmax[1] = fmaxf(rmax[1], fmaxf(s2, s3));
            }
        }

        #pragma unroll
        for (int i = 0; i < 2; i++) {
            float v = rmax[i];
            v = fmaxf(v, __shfl_xor_sync(0xffffffffu, v, 1));
            v = fmaxf(v, __shfl_xor_sync(0xffffffffu, v, 2));
            rmax[i] = v;
        }
    }
    __syncthreads();

    // Exact fp32 rescore: 8-lane quad per candidate (4 candidates in flight
    // per warp). Lane covers 16 dims; intra-quad shuffle-add; cross-quad
    // argmax with ties -> lowest index.
    {
        const int ql = lane & 7;      // lane within quad
        const int q  = lane >> 3;     // quad id (0..3)
        for (int rr = 0; rr < 16; rr++) {
            const int lr  = wid * 16 + rr;
            const int row = blockIdx.x * 64 + lr;
            const int cnt = (int)sCnt[lr];
            const float xx = g_xx[row];

            float bestv = -FLT_MAX;
            int   bestk = 0x7FFFFFFF;

            if (cnt <= CAND_CAP) {
                // x dims for this lane (same across quads -> L1 broadcast)
                float4 xa[4];
                const float4* xr = (const float4*)(x + (size_t)row * DDIM);
                #pragma unroll
                for (int it = 0; it < 4; it++) xa[it] = xr[it * 8 + ql];

                for (int j0 = 0; j0 < cnt; j0 += 4) {
                    const int j  = j0 + q;
                    const int jc = (j < cnt) ? j : (cnt - 1);
                    const int kq = sCand[lr * CAND_CAP + jc];
                    const float4* er = (const float4*)(embed + (size_t)kq * DDIM);
                    float a0 = 0.f, a1 = 0.f, a2 = 0.f, a3 = 0.f;
                    #pragma unroll
                    for (int it = 0; it < 4; it++) {
                        const float4 ea = er[it * 8 + ql];
                        a0 = fmaf(xa[it].x, ea.x, a0);
                        a1 = fmaf(xa[it].y, ea.y, a1);
                        a2 = fmaf(xa[it].z, ea.z, a2);
                        a3 = fmaf(xa[it].w, ea.w, a3);
                    }
                    float part = (a0 + a1) + (a2 + a3);
                    part += __shfl_xor_sync(0xffffffffu, part, 1);
                    part += __shfl_xor_sync(0xffffffffu, part, 2);
                    part += __shfl_xor_sync(0xffffffffu, part, 4);
                    const float dist = (-xx + 2.0f * part) - g_ee[kq];
                    if (j < cnt &&
                        (dist > bestv || (dist == bestv && kq < bestk))) {
                        bestv = dist; bestk = kq;
                    }
                }
            } else {
                // Rare overflow: exact full scan, lane-strided.
                const float4* xr = (const float4*)(x + (size_t)row * DDIM);
                for (int k = lane; k < KCODES; k += 32) {
                    const float4* er = (const float4*)(embed + (size_t)k * DDIM);
                    float a0 = 0.f, a1 = 0.f, a2 = 0.f, a3 = 0.f;
                    #pragma unroll 8
                    for (int i = 0; i < 32; i++) {
                        float4 va = xr[i], ea = er[i];
                        a0 = fmaf(va.x, ea.x, a0);
                        a1 = fmaf(va.y, ea.y, a1);
                        a2 = fmaf(va.z, ea.z, a2);
                        a3 = fmaf(va.w, ea.w, a3);
                    }
                    const float dist = (-xx + 2.0f * ((a0 + a1) + (a2 + a3))) - g_ee[k];
                    if (dist > bestv || (dist == bestv && k < bestk)) {
                        bestv = dist; bestk = k;
                    }
                }
                // bring lanes of each quad to a common best so the 2-step
                // cross-quad reduce below remains sufficient
                #pragma unroll
                for (int o = 1; o <= 4; o <<= 1) {
                    const float ov = __shfl_xor_sync(0xffffffffu, bestv, o);
                    const int   ok = __shfl_xor_sync(0xffffffffu, bestk, o);
                    if (ov > bestv || (ov == bestv && ok < bestk)) { bestv = ov; bestk = ok; }
                }
            }

            // Cross-quad argmax (lanes within a quad already agree).
            #pragma unroll
            for (int o = 8; o <= 16; o <<= 1) {
                const float ov = __shfl_xor_sync(0xffffffffu, bestv, o);
                const int   ok = __shfl_xor_sync(0xffffffffu, bestk, o);
                if (ov > bestv || (ov == bestv && ok < bestk)) { bestv = ov; bestk = ok; }
            }
            if (lane == 0) {
                fidx[lr] = bestk;
                g_idx[row] = bestk;
                out[IND_OFF + (size_t)row] = (float)bestk;
            }
        }
    }
    __syncthreads();

    // quantized = embed[idx] (coalesced float4 gather-copy)
    for (int v = tid; v < 64 * 32; v += 128) {
        const int r = v >> 5, seg = v & 31;
        const float4* ep = (const float4*)(embed + (size_t)fidx[r] * DDIM);
        ((float4*)out)[(size_t)(blockIdx.x * 64 + r) * 32 + seg] = ep[seg];
    }
}

// ---------------------------------------------------------------------------
// Scatter-add via vector RED: 8 rows/block, 32 lanes x 4 dims per row.
__global__ void k_scatter(const float* __restrict__ x) {
    const int row = blockIdx.x * 8 + (threadIdx.x >> 5);
    const int d4  = (threadIdx.x & 31) * 4;
    const int idx = g_idx[row];
    const float4 v = *(const float4*)(x + (size_t)row * DDIM + d4);
    float* dst = &g_embed_sum[(size_t)idx * DDIM + d4];
    asm volatile("red.global.add.v4.f32 [%0], {%1,%2,%3,%4};"
                 :: "l"(dst), "f"(v.x), "f"(v.y), "f"(v.z), "f"(v.w)
                 : "memory");
    if (d4 == 0) atomicAdd(&g_counts[idx], 1.0f);
}

__global__ void k_c1(const float* __restrict__ cs, float* __restrict__ out) {
    int i = threadIdx.x;  // 1024
    float ncs = cs[i] * DECAYF + OMDF * g_counts[i];
    out[NCS_OFF + (size_t)i] = ncs;
    float v = ncs;
    #pragma unroll
    for (int o = 16; o > 0; o >>= 1) v += __shfl_down_sync(0xffffffffu, v, o);
    __shared__ float s[32];
    if ((i & 31) == 0) s[i >> 5] = v;
    __syncthreads();
    if (i < 32) {
        float w = s[i];
        #pragma unroll
        for (int o = 16; o > 0; o >>= 1) w += __shfl_down_sync(0xffffffffu, w, o);
        if (i == 0) g_total = w;
    }
}

__global__ void k_c2(const float* __restrict__ ea, float* __restrict__ out) {
    int k = blockIdx.x;
    int d = threadIdx.x;  // 128
    size_t off = (size_t)k * DDIM + d;
    float nea = ea[off] * DECAYF + OMDF * g_embed_sum[off];
    out[NEA_OFF + off] = nea;
    float total = g_total;
    float ncs   = out[NCS_OFF + (size_t)k];
    float sm    = (ncs + EPSF) / (total + KEPSF) * total;
    out[EMB_OFF + off] = nea / sm;
}

// ---------------------------------------------------------------------------
extern "C" void kernel_launch(void* const* d_in, const int* in_sizes, int n_in,
                              void* d_out, int out_size) {
    const float* x  = (const float*)d_in[0];
    const float* e  = (const float*)d_in[1];
    const float* ea = (const float*)d_in[2];
    const float* cs = (const float*)d_in[3];
    float* out = (float*)d_out;

    k_init<<<KCODES, 128>>>(e);                 // launch 1 (init + packE)
    k_packX<<<N_ROWS / 4, 256>>>(x);            // launch 2
    k_score<<<N_ROWS / 64, 128>>>(x, e, out);   // launch 3
    k_scatter<<<N_ROWS / 8, 256>>>(x);          // launch 4
    k_c1<<<1, 1024>>>(cs, out);                 // launch 5
    k_c2<<<KCODES, 128>>>(ea, out);             // launch 6
}

// round 10
// speedup vs baseline: 3.3829x; 1.0751x over previous
#include <cuda_runtime.h>
#include <cuda_bf16.h>
#include <cstdint>
#include <float.h>

// Problem constants
#define N_ROWS  (64 * 2048)   // 131072
#define DDIM    128
#define KCODES  1024

// Output layout (fp32, concatenated in reference return order)
#define Q_OFF    ((size_t)0)
#define IND_OFF  ((size_t)16777216)
#define EMB_OFF  ((size_t)16908288)
#define NCS_OFF  ((size_t)17039360)
#define NEA_OFF  ((size_t)17040384)

#define DECAYF   0.99f
#define OMDF     0.01f
#define EPSF     1e-5f
#define KEPSF    0.01024f

#define SCREEN_T 0.6f
#define CAND_CAP 64

// ---------------------------------------------------------------------------
// Scratch (__device__ globals; no allocation allowed)
__device__ float    g_counts[KCODES];
__device__ float    g_embed_sum[KCODES * DDIM];
__device__ float    g_total;
__device__ float    g_ee[KCODES];
__device__ float    g_xx[N_ROWS];
__device__ int      g_idx[N_ROWS];
__device__ uint32_t g_X16[(size_t)N_ROWS * 64];  // bf16x2-packed X rows (32 MB)
__device__ uint4    g_E16[KCODES * 16];          // bf16 E, XOR-swizzled 16B units (256 KB)

// ---------------------------------------------------------------------------
// Init: zero accumulators + per-code squared norms + pack E (bf16, swizzled).
__global__ void k_init(const float* __restrict__ embed) {
    int k = blockIdx.x;       // 1024
    int t = threadIdx.x;      // 128
    g_embed_sum[(size_t)k * DDIM + t] = 0.0f;
    if (t == 0) g_counts[k] = 0.0f;
    if (k == 0 && t == 0) g_total = 0.0f;

    float v = embed[(size_t)k * DDIM + t];
    v *= v;
    __shared__ float s[4];
    #pragma unroll
    for (int o = 16; o > 0; o >>= 1) v += __shfl_down_sync(0xffffffffu, v, o);
    if ((t & 31) == 0) s[t >> 5] = v;
    __syncthreads();
    if (t == 0) g_ee[k] = s[0] + s[1] + s[2] + s[3];

    if (t < 16) {
        const float* src = embed + (size_t)k * DDIM + t * 8;
        float4 a = ((const float4*)src)[0];
        float4 b = ((const float4*)src)[1];
        __nv_bfloat162 p0 = __float22bfloat162_rn(make_float2(a.x, a.y));
        __nv_bfloat162 p1 = __float22bfloat162_rn(make_float2(a.z, a.w));
        __nv_bfloat162 p2 = __float22bfloat162_rn(make_float2(b.x, b.y));
        __nv_bfloat162 p3 = __float22bfloat162_rn(make_float2(b.z, b.w));
        uint4 o4;
        o4.x = *(uint32_t*)&p0; o4.y = *(uint32_t*)&p1;
        o4.z = *(uint32_t*)&p2; o4.w = *(uint32_t*)&p3;
        g_E16[k * 16 + (t ^ (k & 7))] = o4;
    }
}

// Pack X rows to bf16x2 + compute row squared norms. 4 rows/block, 64 thr/row.
__global__ void k_packX(const float* __restrict__ x) {
    int tid = threadIdx.x;           // 256
    int r   = blockIdx.x * 4 + (tid >> 6);
    int i   = tid & 63;
    float2 v = ((const float2*)(x + (size_t)r * DDIM))[i];
    __nv_bfloat162 b = __float22bfloat162_rn(v);
    g_X16[(size_t)r * 64 + i] = *(uint32_t*)&b;
    float ss = v.x * v.x + v.y * v.y;
    #pragma unroll
    for (int o = 16; o > 0; o >>= 1) ss += __shfl_down_sync(0xffffffffu, ss, o);
    __shared__ float s[8];
    if ((tid & 31) == 0) s[tid >> 5] = ss;
    __syncthreads();
    if ((tid & 63) == 0) g_xx[r] = s[(tid >> 5)] + s[(tid >> 5) + 1];
}

// ---------------------------------------------------------------------------
__device__ __forceinline__ uint32_t smem_u32(const void* p) {
    uint32_t a;
    asm("{ .reg .u64 t; cvta.to.shared.u64 t, %1; cvt.u32.u64 %0, t; }" : "=r"(a) : "l"(p));
    return a;
}

#define MMA_BF16(accp, af, bb0, bb1) \
    asm volatile( \
        "mma.sync.aligned.m16n8k16.row.col.f32.bf16.bf16.f32 " \
        "{%0,%1,%2,%3}, {%4,%5,%6,%7}, {%8,%9}, {%0,%1,%2,%3};" \
        : "+f"((accp)[0]), "+f"((accp)[1]), "+f"((accp)[2]), "+f"((accp)[3]) \
        : "r"((af)[0]), "r"((af)[1]), "r"((af)[2]), "r"((af)[3]), \
          "r"(bb0), "r"(bb1))

// MMA over one 16-code batch (1 m-tile of 16 rows): fills acc[2][4]
#define BATCH_MMA(b) \
    { \
        const uint32_t rowaddr = smEa + (((b) * 16 + ctile * 8 + row8) << 8); \
        _Pragma("unroll") \
        for (int n2 = 0; n2 < 2; n2++) \
            _Pragma("unroll") \
            for (int i = 0; i < 4; i++) acc[n2][i] = 0.0f; \
        _Pragma("unroll") \
        for (int ks = 0; ks < 8; ks++) { \
            uint32_t b0, b1, b2, b3; \
            asm volatile( \
                "ldmatrix.sync.aligned.m8n8.x4.shared.b16 {%0,%1,%2,%3}, [%4];" \
                : "=r"(b0), "=r"(b1), "=r"(b2), "=r"(b3) \
                : "r"(rowaddr + (((2 * ks + khalf) ^ row8) << 4))); \
            MMA_BF16(acc[0], afr[ks], b0, b1); \
            MMA_BF16(acc[1], afr[ks], b2, b3); \
        } \
    }

// Compute the 8 batch scores into sc[2][4]
#define BATCH_SCORES(b) \
    _Pragma("unroll") \
    for (int n2 = 0; n2 < 2; n2++) { \
        const int le0 = (b) * 16 + n2 * 8 + 2 * tig; \
        const float ee0 = sEE[le0]; \
        const float ee1 = sEE[le0 + 1]; \
        sc[0][n2 * 2 + 0] = fmaf(2.0f, acc[n2][0], -ee0); \
        sc[0][n2 * 2 + 1] = fmaf(2.0f, acc[n2][1], -ee1); \
        sc[1][n2 * 2 + 0] = fmaf(2.0f, acc[n2][2], -ee0); \
        sc[1][n2 * 2 + 1] = fmaf(2.0f, acc[n2][3], -ee1); \
    }

// ---------------------------------------------------------------------------
// HMMA two-level screening + quad-cooperative exact fp32 rescore + fused
// quantized write and EMA scatter.
// CTA = 128 threads (4 warps), each warp owns 16 rows -> CTA covers 64 rows.
__global__ __launch_bounds__(128, 6) void k_score(const float* __restrict__ x,
                                                  const float* __restrict__ embed,
                                                  float* __restrict__ out) {
    __shared__ __align__(16) uint4 smE[1024];       // 16 KB: E tile
    __shared__ float     sEE[64];
    __shared__ uint16_t  sCand[64 * CAND_CAP];      // 8 KB
    __shared__ uint32_t  sCnt[64];
    __shared__ int       fidx[64];

    const int tid  = threadIdx.x;
    const int wid  = tid >> 5;
    const int lane = tid & 31;
    const int g    = lane >> 2;
    const int tig  = lane & 3;
    const int rbase = blockIdx.x * 64 + wid * 16;

    if (tid < 64) sCnt[tid] = 0;

    // Load A fragments: 8 k-steps x 4 regs (this warp's 16 rows).
    uint32_t afr[8][4];
    {
        const size_t rA = (size_t)(rbase + g) * 64;
        const size_t rB = rA + 8 * 64;
        #pragma unroll
        for (int ks = 0; ks < 8; ks++) {
            afr[ks][0] = g_X16[rA + 8 * ks + tig];
            afr[ks][1] = g_X16[rB + 8 * ks + tig];
            afr[ks][2] = g_X16[rA + 8 * ks + 4 + tig];
            afr[ks][3] = g_X16[rB + 8 * ks + 4 + tig];
        }
    }

    float rmax[2];
    rmax[0] = -FLT_MAX; rmax[1] = -FLT_MAX;

    const uint32_t smEa = smem_u32(smE);
    const int row8  = lane & 7;
    const int ctile = (lane >> 4) & 1;
    const int khalf = (lane >> 3) & 1;

    for (int c = 0; c < 16; c++) {    // 16 chunks of 64 codes
        __syncthreads();
        {
            const uint4* ep = g_E16 + c * 1024;
            #pragma unroll
            for (int i = 0; i < 8; i++) smE[tid + i * 128] = ep[tid + i * 128];
            if (tid < 64) sEE[tid] = g_ee[c * 64 + tid];
        }
        __syncthreads();

        float acc[2][4];
        float sc[2][4];

        if (c == 0) {
            // Max-only warm-up over chunk 0 (no appends).
            #pragma unroll
            for (int b = 0; b < 4; b++) {
                BATCH_MMA(b);
                BATCH_SCORES(b);
                #pragma unroll
                for (int h = 0; h < 2; h++)
                    rmax[h] = fmaxf(rmax[h],
                                    fmaxf(fmaxf(sc[h][0], sc[h][1]),
                                          fmaxf(sc[h][2], sc[h][3])));
            }
            #pragma unroll
            for (int i = 0; i < 2; i++) {
                float v = rmax[i];
                v = fmaxf(v, __shfl_xor_sync(0xffffffffu, v, 1));
                v = fmaxf(v, __shfl_xor_sync(0xffffffffu, v, 2));
                rmax[i] = v;
            }
        }

        #pragma unroll
        for (int b = 0; b < 4; b++) {
            BATCH_MMA(b);
            BATCH_SCORES(b);

            // Two-level screening: compare the per-row batch max once.
            #pragma unroll
            for (int h = 0; h < 2; h++) {
                const float thr = rmax[h] - SCREEN_T;
                const float m = fmaxf(fmaxf(sc[h][0], sc[h][1]),
                                      fmaxf(sc[h][2], sc[h][3]));
                if (m >= thr) {    // rare
                    const int lr = wid * 16 + h * 8 + g;
                    #pragma unroll
                    for (int n2 = 0; n2 < 2; n2++)
                        #pragma unroll
                        for (int j = 0; j < 2; j++)
                            if (sc[h][n2 * 2 + j] >= thr) {
                                uint32_t n = atomicAdd(&sCnt[lr], 1u);
                                if (n < CAND_CAP)
                                    sCand[lr * CAND_CAP + n] =
                                        (uint16_t)(c * 64 + b * 16 + n2 * 8 + 2 * tig + j);
                            }
                }
                rmax[h] = fmaxf(rmax[h], m);
            }
        }

        #pragma unroll
        for (int i = 0; i < 2; i++) {
            float v = rmax[i];
            v = fmaxf(v, __shfl_xor_sync(0xffffffffu, v, 1));
            v = fmaxf(v, __shfl_xor_sync(0xffffffffu, v, 2));
            rmax[i] = v;
        }
    }
    __syncthreads();

    // Exact fp32 rescore: 8-lane quad per candidate.
    {
        const int ql = lane & 7;
        const int q  = lane >> 3;
        for (int rr = 0; rr < 16; rr++) {
            const int lr  = wid * 16 + rr;
            const int row = blockIdx.x * 64 + lr;
            const int cnt = (int)sCnt[lr];
            const float xx = g_xx[row];

            float bestv = -FLT_MAX;
            int   bestk = 0x7FFFFFFF;

            if (cnt <= CAND_CAP) {
                float4 xa[4];
                const float4* xr = (const float4*)(x + (size_t)row * DDIM);
                #pragma unroll
                for (int it = 0; it < 4; it++) xa[it] = xr[it * 8 + ql];

                for (int j0 = 0; j0 < cnt; j0 += 4) {
                    const int j  = j0 + q;
                    const int jc = (j < cnt) ? j : (cnt - 1);
                    const int kq = sCand[lr * CAND_CAP + jc];
                    const float4* er = (const float4*)(embed + (size_t)kq * DDIM);
                    float a0 = 0.f, a1 = 0.f, a2 = 0.f, a3 = 0.f;
                    #pragma unroll
                    for (int it = 0; it < 4; it++) {
                        const float4 ea = er[it * 8 + ql];
                        a0 = fmaf(xa[it].x, ea.x, a0);
                        a1 = fmaf(xa[it].y, ea.y, a1);
                        a2 = fmaf(xa[it].z, ea.z, a2);
                        a3 = fmaf(xa[it].w, ea.w, a3);
                    }
                    float part = (a0 + a1) + (a2 + a3);
                    part += __shfl_xor_sync(0xffffffffu, part, 1);
                    part += __shfl_xor_sync(0xffffffffu, part, 2);
                    part += __shfl_xor_sync(0xffffffffu, part, 4);
                    const float dist = (-xx + 2.0f * part) - g_ee[kq];
                    if (j < cnt &&
                        (dist > bestv || (dist == bestv && kq < bestk))) {
                        bestv = dist; bestk = kq;
                    }
                }
            } else {
                const float4* xr = (const float4*)(x + (size_t)row * DDIM);
                for (int k = lane; k < KCODES; k += 32) {
                    const float4* er = (const float4*)(embed + (size_t)k * DDIM);
                    float a0 = 0.f, a1 = 0.f, a2 = 0.f, a3 = 0.f;
                    #pragma unroll 8
                    for (int i = 0; i < 32; i++) {
                        float4 va = xr[i], ea = er[i];
                        a0 = fmaf(va.x, ea.x, a0);
                        a1 = fmaf(va.y, ea.y, a1);
                        a2 = fmaf(va.z, ea.z, a2);
                        a3 = fmaf(va.w, ea.w, a3);
                    }
                    const float dist = (-xx + 2.0f * ((a0 + a1) + (a2 + a3))) - g_ee[k];
                    if (dist > bestv || (dist == bestv && k < bestk)) {
                        bestv = dist; bestk = k;
                    }
                }
                #pragma unroll
                for (int o = 1; o <= 4; o <<= 1) {
                    const float ov = __shfl_xor_sync(0xffffffffu, bestv, o);
                    const int   ok = __shfl_xor_sync(0xffffffffu, bestk, o);
                    if (ov > bestv || (ov == bestv && ok < bestk)) { bestv = ov; bestk = ok; }
                }
            }

            #pragma unroll
            for (int o = 8; o <= 16; o <<= 1) {
                const float ov = __shfl_xor_sync(0xffffffffu, bestv, o);
                const int   ok = __shfl_xor_sync(0xffffffffu, bestk, o);
                if (ov > bestv || (ov == bestv && ok < bestk)) { bestv = ov; bestk = ok; }
            }
            if (lane == 0) {
                fidx[lr] = bestk;
                g_idx[row] = bestk;
                out[IND_OFF + (size_t)row] = (float)bestk;
            }
        }
    }
    __syncthreads();

    // Fused epilogue: quantized = embed[idx] write + EMA scatter (RED).
    for (int v = tid; v < 64 * 32; v += 128) {
        const int r = v >> 5, seg = v & 31;
        const int idx = fidx[r];
        const float4* ep = (const float4*)(embed + (size_t)idx * DDIM);
        ((float4*)out)[(size_t)(blockIdx.x * 64 + r) * 32 + seg] = ep[seg];

        const float4 xv =
            ((const float4*)(x + (size_t)(blockIdx.x * 64 + r) * DDIM))[seg];
        float* dst = &g_embed_sum[(size_t)idx * DDIM + seg * 4];
        asm volatile("red.global.add.v4.f32 [%0], {%1,%2,%3,%4};"
                     :: "l"(dst), "f"(xv.x), "f"(xv.y), "f"(xv.z), "f"(xv.w)
                     : "memory");
    }
    if (tid < 64) atomicAdd(&g_counts[fidx[tid]], 1.0f);
}

// ---------------------------------------------------------------------------
__global__ void k_c1(const float* __restrict__ cs, float* __restrict__ out) {
    int i = threadIdx.x;  // 1024
    float ncs = cs[i] * DECAYF + OMDF * g_counts[i];
    out[NCS_OFF + (size_t)i] = ncs;
    float v = ncs;
    #pragma unroll
    for (int o = 16; o > 0; o >>= 1) v += __shfl_down_sync(0xffffffffu, v, o);
    __shared__ float s[32];
    if ((i & 31) == 0) s[i >> 5] = v;
    __syncthreads();
    if (i < 32) {
        float w = s[i];
        #pragma unroll
        for (int o = 16; o > 0; o >>= 1) w += __shfl_down_sync(0xffffffffu, w, o);
        if (i == 0) g_total = w;
    }
}

__global__ void k_c2(const float* __restrict__ ea, float* __restrict__ out) {
    int k = blockIdx.x;
    int d = threadIdx.x;  // 128
    size_t off = (size_t)k * DDIM + d;
    float nea = ea[off] * DECAYF + OMDF * g_embed_sum[off];
    out[NEA_OFF + off] = nea;
    float total = g_total;
    float ncs   = out[NCS_OFF + (size_t)k];
    float sm    = (ncs + EPSF) / (total + KEPSF) * total;
    out[EMB_OFF + off] = nea / sm;
}

// ---------------------------------------------------------------------------
extern "C" void kernel_launch(void* const* d_in, const int* in_sizes, int n_in,
                              void* d_out, int out_size) {
    const float* x  = (const float*)d_in[0];
    const float* e  = (const float*)d_in[1];
    const float* ea = (const float*)d_in[2];
    const float* cs = (const float*)d_in[3];
    float* out = (float*)d_out;

    k_init<<<KCODES, 128>>>(e);                 // launch 1 (init + packE)
    k_packX<<<N_ROWS / 4, 256>>>(x);            // launch 2
    k_score<<<N_ROWS / 64, 128>>>(x, e, out);   // launch 3 (sweep+rescore+scatter)
    k_c1<<<1, 1024>>>(cs, out);                 // launch 4
    k_c2<<<KCODES, 128>>>(ea, out);             // launch 5
}

// round 11
// speedup vs baseline: 4.0197x; 1.1883x over previous
#include <cuda_runtime.h>
#include <cuda_bf16.h>
#include <cstdint>
#include <float.h>

// Problem constants
#define N_ROWS  (64 * 2048)   // 131072
#define DDIM    128
#define KCODES  1024

// Output layout (fp32, concatenated in reference return order)
#define Q_OFF    ((size_t)0)
#define IND_OFF  ((size_t)16777216)
#define EMB_OFF  ((size_t)16908288)
#define NCS_OFF  ((size_t)17039360)
#define NEA_OFF  ((size_t)17040384)

#define DECAYF   0.99f
#define OMDF     0.01f
#define EPSF     1e-5f
#define KEPSF    0.01024f

#define SCREEN_T 0.6f
#define CAND_CAP 64

// ---------------------------------------------------------------------------
// Scratch (__device__ globals; no allocation allowed)
__device__ float    g_counts[KCODES];
__device__ float    g_embed_sum[KCODES * DDIM];
__device__ float    g_ee[KCODES];
__device__ int      g_idx[N_ROWS];
__device__ uint4    g_E16[KCODES * 16];   // bf16 E, XOR-swizzled 16B units (256 KB)

// ---------------------------------------------------------------------------
// Init: zero accumulators + per-code squared norms + pack E (bf16, swizzled).
__global__ void k_init(const float* __restrict__ embed) {
    int k = blockIdx.x;       // 1024
    int t = threadIdx.x;      // 128
    g_embed_sum[(size_t)k * DDIM + t] = 0.0f;
    if (t == 0) g_counts[k] = 0.0f;

    float v = embed[(size_t)k * DDIM + t];
    v *= v;
    __shared__ float s[4];
    #pragma unroll
    for (int o = 16; o > 0; o >>= 1) v += __shfl_down_sync(0xffffffffu, v, o);
    if ((t & 31) == 0) s[t >> 5] = v;
    __syncthreads();
    if (t == 0) g_ee[k] = s[0] + s[1] + s[2] + s[3];

    if (t < 16) {
        const float* src = embed + (size_t)k * DDIM + t * 8;
        float4 a = ((const float4*)src)[0];
        float4 b = ((const float4*)src)[1];
        __nv_bfloat162 p0 = __float22bfloat162_rn(make_float2(a.x, a.y));
        __nv_bfloat162 p1 = __float22bfloat162_rn(make_float2(a.z, a.w));
        __nv_bfloat162 p2 = __float22bfloat162_rn(make_float2(b.x, b.y));
        __nv_bfloat162 p3 = __float22bfloat162_rn(make_float2(b.z, b.w));
        uint4 o4;
        o4.x = *(uint32_t*)&p0; o4.y = *(uint32_t*)&p1;
        o4.z = *(uint32_t*)&p2; o4.w = *(uint32_t*)&p3;
        g_E16[k * 16 + (t ^ (k & 7))] = o4;
    }
}

// ---------------------------------------------------------------------------
__device__ __forceinline__ uint32_t smem_u32(const void* p) {
    uint32_t a;
    asm("{ .reg .u64 t; cvta.to.shared.u64 t, %1; cvt.u32.u64 %0, t; }" : "=r"(a) : "l"(p));
    return a;
}

#define MMA_BF16(accp, af, bb0, bb1) \
    asm volatile( \
        "mma.sync.aligned.m16n8k16.row.col.f32.bf16.bf16.f32 " \
        "{%0,%1,%2,%3}, {%4,%5,%6,%7}, {%8,%9}, {%0,%1,%2,%3};" \
        : "+f"((accp)[0]), "+f"((accp)[1]), "+f"((accp)[2]), "+f"((accp)[3]) \
        : "r"((af)[0]), "r"((af)[1]), "r"((af)[2]), "r"((af)[3]), \
          "r"(bb0), "r"(bb1))

// MMA over one 16-code batch (1 m-tile of 16 rows): fills acc[2][4]
#define BATCH_MMA(b) \
    { \
        const uint32_t rowaddr = smEa + (((b) * 16 + ctile * 8 + row8) << 8); \
        _Pragma("unroll") \
        for (int n2 = 0; n2 < 2; n2++) \
            _Pragma("unroll") \
            for (int i = 0; i < 4; i++) acc[n2][i] = 0.0f; \
        _Pragma("unroll") \
        for (int ks = 0; ks < 8; ks++) { \
            uint32_t b0, b1, b2, b3; \
            asm volatile( \
                "ldmatrix.sync.aligned.m8n8.x4.shared.b16 {%0,%1,%2,%3}, [%4];" \
                : "=r"(b0), "=r"(b1), "=r"(b2), "=r"(b3) \
                : "r"(rowaddr + (((2 * ks + khalf) ^ row8) << 4))); \
            MMA_BF16(acc[0], afr[ks], b0, b1); \
            MMA_BF16(acc[1], afr[ks], b2, b3); \
        } \
    }

// Compute the 8 batch scores into sc[2][4] (ee pairs from float2 smem)
#define BATCH_SCORES(b) \
    _Pragma("unroll") \
    for (int n2 = 0; n2 < 2; n2++) { \
        const float2 ee = sEE2[(b) * 8 + n2 * 4 + tig]; \
        sc[0][n2 * 2 + 0] = fmaf(2.0f, acc[n2][0], -ee.x); \
        sc[0][n2 * 2 + 1] = fmaf(2.0f, acc[n2][1], -ee.y); \
        sc[1][n2 * 2 + 0] = fmaf(2.0f, acc[n2][2], -ee.x); \
        sc[1][n2 * 2 + 1] = fmaf(2.0f, acc[n2][3], -ee.y); \
    }

// ---------------------------------------------------------------------------
// HMMA two-level screening + quad-cooperative exact fp32 rescore + fused
// quantized write and EMA scatter. A fragments converted from x in-kernel.
// CTA = 128 threads (4 warps), each warp owns 16 rows -> CTA covers 64 rows.
__global__ __launch_bounds__(128, 6) void k_score(const float* __restrict__ x,
                                                  const float* __restrict__ embed,
                                                  float* __restrict__ out) {
    __shared__ __align__(16) uint4 smE[1024];       // 16 KB: E tile
    __shared__ float2    sEE2[32];
    __shared__ uint16_t  sCand[64 * CAND_CAP];      // 8 KB
    __shared__ uint32_t  sCnt[64];
    __shared__ int       fidx[64];

    const int tid  = threadIdx.x;
    const int wid  = tid >> 5;
    const int lane = tid & 31;
    const int g    = lane >> 2;
    const int tig  = lane & 3;
    const int rbase = blockIdx.x * 64 + wid * 16;

    if (tid < 64) sCnt[tid] = 0;

    // Build A fragments directly from x (fp32 -> bf16x2, same rounding as a
    // separate pack pass would give). 8 k-steps x 4 regs, this warp's 16 rows.
    uint32_t afr[8][4];
    {
        const float* xr0 = x + (size_t)(rbase + g) * DDIM + 2 * tig;
        const float* xr1 = xr0 + 8 * DDIM;
        #pragma unroll
        for (int ks = 0; ks < 8; ks++) {
            const float2 v0 = *(const float2*)(xr0 + 16 * ks);
            const float2 v1 = *(const float2*)(xr1 + 16 * ks);
            const float2 v2 = *(const float2*)(xr0 + 16 * ks + 8);
            const float2 v3 = *(const float2*)(xr1 + 16 * ks + 8);
            __nv_bfloat162 b0 = __float22bfloat162_rn(v0);
            __nv_bfloat162 b1 = __float22bfloat162_rn(v1);
            __nv_bfloat162 b2 = __float22bfloat162_rn(v2);
            __nv_bfloat162 b3 = __float22bfloat162_rn(v3);
            afr[ks][0] = *(uint32_t*)&b0;
            afr[ks][1] = *(uint32_t*)&b1;
            afr[ks][2] = *(uint32_t*)&b2;
            afr[ks][3] = *(uint32_t*)&b3;
        }
    }

    float rmax[2];
    rmax[0] = -FLT_MAX; rmax[1] = -FLT_MAX;

    const uint32_t smEa = smem_u32(smE);
    const int row8  = lane & 7;
    const int ctile = (lane >> 4) & 1;
    const int khalf = (lane >> 3) & 1;

    for (int c = 0; c < 16; c++) {    // 16 chunks of 64 codes
        __syncthreads();
        {
            const uint4* ep = g_E16 + c * 1024;
            #pragma unroll
            for (int i = 0; i < 8; i++) smE[tid + i * 128] = ep[tid + i * 128];
            if (tid < 32) sEE2[tid] = ((const float2*)(g_ee + c * 64))[tid];
        }
        __syncthreads();

        float acc[2][4];
        float sc[2][4];

        if (c == 0) {
            // Max-only warm-up over chunk 0 (no appends).
            #pragma unroll
            for (int b = 0; b < 4; b++) {
                BATCH_MMA(b);
                BATCH_SCORES(b);
                #pragma unroll
                for (int h = 0; h < 2; h++)
                    rmax[h] = fmaxf(rmax[h],
                                    fmaxf(fmaxf(sc[h][0], sc[h][1]),
                                          fmaxf(sc[h][2], sc[h][3])));
            }
            #pragma unroll
            for (int i = 0; i < 2; i++) {
                float v = rmax[i];
                v = fmaxf(v, __shfl_xor_sync(0xffffffffu, v, 1));
                v = fmaxf(v, __shfl_xor_sync(0xffffffffu, v, 2));
                rmax[i] = v;
            }
        }

        #pragma unroll
        for (int b = 0; b < 4; b++) {
            BATCH_MMA(b);
            BATCH_SCORES(b);

            // Two-level screening: compare the per-row batch max once.
            #pragma unroll
            for (int h = 0; h < 2; h++) {
                const float thr = rmax[h] - SCREEN_T;
                const float m = fmaxf(fmaxf(sc[h][0], sc[h][1]),
                                      fmaxf(sc[h][2], sc[h][3]));
                if (m >= thr) {    // rare
                    const int lr = wid * 16 + h * 8 + g;
                    #pragma unroll
                    for (int n2 = 0; n2 < 2; n2++)
                        #pragma unroll
                        for (int j = 0; j < 2; j++)
                            if (sc[h][n2 * 2 + j] >= thr) {
                                uint32_t n = atomicAdd(&sCnt[lr], 1u);
                                if (n < CAND_CAP)
                                    sCand[lr * CAND_CAP + n] =
                                        (uint16_t)(c * 64 + b * 16 + n2 * 8 + 2 * tig + j);
                            }
                }
                rmax[h] = fmaxf(rmax[h], m);
            }
        }

        #pragma unroll
        for (int i = 0; i < 2; i++) {
            float v = rmax[i];
            v = fmaxf(v, __shfl_xor_sync(0xffffffffu, v, 1));
            v = fmaxf(v, __shfl_xor_sync(0xffffffffu, v, 2));
            rmax[i] = v;
        }
    }
    __syncthreads();

    // Exact fp32 rescore: 8-lane quad per candidate.
    // dist' = 2*dot - ee (the -xx term is row-constant: argmax-equivalent).
    {
        const int ql = lane & 7;
        const int q  = lane >> 3;
        for (int rr = 0; rr < 16; rr++) {
            const int lr  = wid * 16 + rr;
            const int row = blockIdx.x * 64 + lr;
            const int cnt = (int)sCnt[lr];

            float bestv = -FLT_MAX;
            int   bestk = 0x7FFFFFFF;

            if (cnt <= CAND_CAP) {
                float4 xa[4];
                const float4* xr = (const float4*)(x + (size_t)row * DDIM);
                #pragma unroll
                for (int it = 0; it < 4; it++) xa[it] = xr[it * 8 + ql];

                for (int j0 = 0; j0 < cnt; j0 += 4) {
                    const int j  = j0 + q;
                    const int jc = (j < cnt) ? j : (cnt - 1);
                    const int kq = sCand[lr * CAND_CAP + jc];
                    const float4* er = (const float4*)(embed + (size_t)kq * DDIM);
                    float a0 = 0.f, a1 = 0.f, a2 = 0.f, a3 = 0.f;
                    #pragma unroll
                    for (int it = 0; it < 4; it++) {
                        const float4 ea = er[it * 8 + ql];
                        a0 = fmaf(xa[it].x, ea.x, a0);
                        a1 = fmaf(xa[it].y, ea.y, a1);
                        a2 = fmaf(xa[it].z, ea.z, a2);
                        a3 = fmaf(xa[it].w, ea.w, a3);
                    }
                    float part = (a0 + a1) + (a2 + a3);
                    part += __shfl_xor_sync(0xffffffffu, part, 1);
                    part += __shfl_xor_sync(0xffffffffu, part, 2);
                    part += __shfl_xor_sync(0xffffffffu, part, 4);
                    const float dist = 2.0f * part - g_ee[kq];
                    if (j < cnt &&
                        (dist > bestv || (dist == bestv && kq < bestk))) {
                        bestv = dist; bestk = kq;
                    }
                }
            } else {
                const float4* xr = (const float4*)(x + (size_t)row * DDIM);
                for (int k = lane; k < KCODES; k += 32) {
                    const float4* er = (const float4*)(embed + (size_t)k * DDIM);
                    float a0 = 0.f, a1 = 0.f, a2 = 0.f, a3 = 0.f;
                    #pragma unroll 8
                    for (int i = 0; i < 32; i++) {
                        float4 va = xr[i], ea = er[i];
                        a0 = fmaf(va.x, ea.x, a0);
                        a1 = fmaf(va.y, ea.y, a1);
                        a2 = fmaf(va.z, ea.z, a2);
                        a3 = fmaf(va.w, ea.w, a3);
                    }
                    const float dist = 2.0f * ((a0 + a1) + (a2 + a3)) - g_ee[k];
                    if (dist > bestv || (dist == bestv && k < bestk)) {
                        bestv = dist; bestk = k;
                    }
                }
                #pragma unroll
                for (int o = 1; o <= 4; o <<= 1) {
                    const float ov = __shfl_xor_sync(0xffffffffu, bestv, o);
                    const int   ok = __shfl_xor_sync(0xffffffffu, bestk, o);
                    if (ov > bestv || (ov == bestv && ok < bestk)) { bestv = ov; bestk = ok; }
                }
            }

            #pragma unroll
            for (int o = 8; o <= 16; o <<= 1) {
                const float ov = __shfl_xor_sync(0xffffffffu, bestv, o);
                const int   ok = __shfl_xor_sync(0xffffffffu, bestk, o);
                if (ov > bestv || (ov == bestv && ok < bestk)) { bestv = ov; bestk = ok; }
            }
            if (lane == 0) {
                fidx[lr] = bestk;
                g_idx[row] = bestk;
                out[IND_OFF + (size_t)row] = (float)bestk;
            }
        }
    }
    __syncthreads();

    // Fused epilogue: quantized = embed[idx] write + EMA scatter (RED).
    for (int v = tid; v < 64 * 32; v += 128) {
        const int r = v >> 5, seg = v & 31;
        const int idx = fidx[r];
        const float4* ep = (const float4*)(embed + (size_t)idx * DDIM);
        ((float4*)out)[(size_t)(blockIdx.x * 64 + r) * 32 + seg] = ep[seg];

        const float4 xv =
            ((const float4*)(x + (size_t)(blockIdx.x * 64 + r) * DDIM))[seg];
        float* dst = &g_embed_sum[(size_t)idx * DDIM + seg * 4];
        asm volatile("red.global.add.v4.f32 [%0], {%1,%2,%3,%4};"
                     :: "l"(dst), "f"(xv.x), "f"(xv.y), "f"(xv.z), "f"(xv.w)
                     : "memory");
    }
    if (tid < 64) atomicAdd(&g_counts[fidx[tid]], 1.0f);
}

// ---------------------------------------------------------------------------
// Final epilogue: new_cluster_size (+ redundant per-block total), new_embed_avg,
// new_embed. Block k handles code k.
__global__ void k_cfin(const float* __restrict__ cs,
                       const float* __restrict__ ea,
                       float* __restrict__ out) {
    const int k = blockIdx.x;    // 1024
    const int d = threadIdx.x;   // 128

    // Redundant total = 0.99*sum(cs) + 0.01*sum(counts) (L2-cached loads).
    float part = 0.0f;
    #pragma unroll
    for (int i = 0; i < 8; i++) {
        const int j = d + i * 128;
        part += cs[j] * DECAYF + OMDF * g_counts[j];
    }
    #pragma unroll
    for (int o = 16; o > 0; o >>= 1) part += __shfl_down_sync(0xffffffffu, part, o);
    __shared__ float s[4];
    if ((d & 31) == 0) s[d >> 5] = part;
    __syncthreads();
    const float total = s[0] + s[1] + s[2] + s[3];

    const float ncs = cs[k] * DECAYF + OMDF * g_counts[k];
    if (d == 0) out[NCS_OFF + (size_t)k] = ncs;

    const size_t off = (size_t)k * DDIM + d;
    const float nea = ea[off] * DECAYF + OMDF * g_embed_sum[off];
    out[NEA_OFF + off] = nea;
    const float sm = (ncs + EPSF) / (total + KEPSF) * total;
    out[EMB_OFF + off] = nea / sm;
}

// ---------------------------------------------------------------------------
extern "C" void kernel_launch(void* const* d_in, const int* in_sizes, int n_in,
                              void* d_out, int out_size) {
    const float* x  = (const float*)d_in[0];
    const float* e  = (const float*)d_in[1];
    const float* ea = (const float*)d_in[2];
    const float* cs = (const float*)d_in[3];
    float* out = (float*)d_out;

    k_init<<<KCODES, 128>>>(e);                 // launch 1 (init + packE)
    k_score<<<N_ROWS / 64, 128>>>(x, e, out);   // launch 2 (everything per-row)
    k_cfin<<<KCODES, 128>>>(cs, ea, out);       // launch 3 (EMA epilogue)
}

// round 12
// speedup vs baseline: 4.7656x; 1.1855x over previous
#include <cuda_runtime.h>
#include <cuda_bf16.h>
#include <cstdint>
#include <float.h>

// Problem constants
#define N_ROWS  (64 * 2048)   // 131072
#define DDIM    128
#define KCODES  1024

// Output layout (fp32, concatenated in reference return order)
#define Q_OFF    ((size_t)0)
#define IND_OFF  ((size_t)16777216)
#define EMB_OFF  ((size_t)16908288)
#define NCS_OFF  ((size_t)17039360)
#define NEA_OFF  ((size_t)17040384)

#define DECAYF   0.99f
#define OMDF     0.01f
#define EPSF     1e-5f
#define KEPSF    0.01024f

#define SCREEN_T 0.6f
#define CAND_CAP 64

// ---------------------------------------------------------------------------
// Scratch (__device__ globals; no allocation allowed)
__device__ float    g_counts[KCODES];
__device__ float    g_embed_sum[KCODES * DDIM];
__device__ float    g_ee[KCODES];
__device__ uint4    g_E16[KCODES * 16];   // bf16 E, XOR-swizzled 16B units (256 KB)

// ---------------------------------------------------------------------------
// Init: zero accumulators + per-code squared norms + pack E (bf16, swizzled).
__global__ void k_init(const float* __restrict__ embed) {
    int k = blockIdx.x;       // 1024
    int t = threadIdx.x;      // 128
    g_embed_sum[(size_t)k * DDIM + t] = 0.0f;
    if (t == 0) g_counts[k] = 0.0f;

    float v = embed[(size_t)k * DDIM + t];
    v *= v;
    __shared__ float s[4];
    #pragma unroll
    for (int o = 16; o > 0; o >>= 1) v += __shfl_down_sync(0xffffffffu, v, o);
    if ((t & 31) == 0) s[t >> 5] = v;
    __syncthreads();
    if (t == 0) g_ee[k] = s[0] + s[1] + s[2] + s[3];

    if (t < 16) {
        const float* src = embed + (size_t)k * DDIM + t * 8;
        float4 a = ((const float4*)src)[0];
        float4 b = ((const float4*)src)[1];
        __nv_bfloat162 p0 = __float22bfloat162_rn(make_float2(a.x, a.y));
        __nv_bfloat162 p1 = __float22bfloat162_rn(make_float2(a.z, a.w));
        __nv_bfloat162 p2 = __float22bfloat162_rn(make_float2(b.x, b.y));
        __nv_bfloat162 p3 = __float22bfloat162_rn(make_float2(b.z, b.w));
        uint4 o4;
        o4.x = *(uint32_t*)&p0; o4.y = *(uint32_t*)&p1;
        o4.z = *(uint32_t*)&p2; o4.w = *(uint32_t*)&p3;
        g_E16[k * 16 + (t ^ (k & 7))] = o4;
    }
}

// ---------------------------------------------------------------------------
__device__ __forceinline__ uint32_t smem_u32(const void* p) {
    uint32_t a;
    asm("{ .reg .u64 t; cvta.to.shared.u64 t, %1; cvt.u32.u64 %0, t; }" : "=r"(a) : "l"(p));
    return a;
}

#define MMA_BF16(accp, af, bb0, bb1) \
    asm volatile( \
        "mma.sync.aligned.m16n8k16.row.col.f32.bf16.bf16.f32 " \
        "{%0,%1,%2,%3}, {%4,%5,%6,%7}, {%8,%9}, {%0,%1,%2,%3};" \
        : "+f"((accp)[0]), "+f"((accp)[1]), "+f"((accp)[2]), "+f"((accp)[3]) \
        : "r"((af)[0]), "r"((af)[1]), "r"((af)[2]), "r"((af)[3]), \
          "r"(bb0), "r"(bb1))

// MMA over one 16-code batch (1 m-tile of 16 rows): fills acc[2][4]
#define BATCH_MMA(b) \
    { \
        const uint32_t rowaddr = smEb + (((b) * 16 + ctile * 8 + row8) << 8); \
        _Pragma("unroll") \
        for (int n2 = 0; n2 < 2; n2++) \
            _Pragma("unroll") \
            for (int i = 0; i < 4; i++) acc[n2][i] = 0.0f; \
        _Pragma("unroll") \
        for (int ks = 0; ks < 8; ks++) { \
            uint32_t b0, b1, b2, b3; \
            asm volatile( \
                "ldmatrix.sync.aligned.m8n8.x4.shared.b16 {%0,%1,%2,%3}, [%4];" \
                : "=r"(b0), "=r"(b1), "=r"(b2), "=r"(b3) \
                : "r"(rowaddr + (((2 * ks + khalf) ^ row8) << 4))); \
            MMA_BF16(acc[0], afr[ks], b0, b1); \
            MMA_BF16(acc[1], afr[ks], b2, b3); \
        } \
    }

// Compute the 8 batch scores into sc[2][4] (ee pairs from float2 smem)
#define BATCH_SCORES(b) \
    _Pragma("unroll") \
    for (int n2 = 0; n2 < 2; n2++) { \
        const float2 ee = sEE2[buf][(b) * 8 + n2 * 4 + tig]; \
        sc[0][n2 * 2 + 0] = fmaf(2.0f, acc[n2][0], -ee.x); \
        sc[0][n2 * 2 + 1] = fmaf(2.0f, acc[n2][1], -ee.y); \
        sc[1][n2 * 2 + 0] = fmaf(2.0f, acc[n2][2], -ee.x); \
        sc[1][n2 * 2 + 1] = fmaf(2.0f, acc[n2][3], -ee.y); \
    }

// Prefetch chunk ch into buffer bf (cp.async, 4x16B per thread + sEE pairs)
#define PREFETCH(ch, bf) \
    { \
        const uint32_t dst = smEbase + (bf) * 16384 + (uint32_t)tid * 16; \
        const uint4* srcp = g_E16 + (ch) * 1024 + tid; \
        _Pragma("unroll") \
        for (int i = 0; i < 4; i++) \
            asm volatile("cp.async.cg.shared.global [%0], [%1], 16;" \
                         :: "r"(dst + i * 4096), "l"(srcp + i * 256) : "memory"); \
        if (tid < 32) sEE2[bf][tid] = ((const float2*)(g_ee + (ch) * 64))[tid]; \
        asm volatile("cp.async.commit_group;" ::: "memory"); \
    }

// ---------------------------------------------------------------------------
// HMMA two-level screening + quad-cooperative exact fp32 rescore + fused
// quantized write and EMA scatter. Double-buffered cp.async E staging.
// CTA = 256 threads (8 warps), each warp owns 16 rows -> CTA covers 128 rows.
__global__ __launch_bounds__(256, 3) void k_score(const float* __restrict__ x,
                                                  const float* __restrict__ embed,
                                                  float* __restrict__ out) {
    __shared__ __align__(16) uint4 smE[2][1024];    // 2 x 16 KB E tiles
    __shared__ float2    sEE2[2][32];
    __shared__ uint16_t  sCand[128 * CAND_CAP];     // 16 KB
    __shared__ uint32_t  sCnt[128];
    __shared__ int       fidx[128];

    const int tid  = threadIdx.x;
    const int wid  = tid >> 5;
    const int lane = tid & 31;
    const int g    = lane >> 2;
    const int tig  = lane & 3;
    const int rbase = blockIdx.x * 128 + wid * 16;

    if (tid < 128) sCnt[tid] = 0;

    const uint32_t smEbase = smem_u32(smE);

    // Prologue: prefetch chunk 0 into buffer 0.
    PREFETCH(0, 0);

    // Build A fragments directly from x (fp32 -> bf16x2). 8 k-steps x 4 regs.
    uint32_t afr[8][4];
    {
        const float* xr0 = x + (size_t)(rbase + g) * DDIM + 2 * tig;
        const float* xr1 = xr0 + 8 * DDIM;
        #pragma unroll
        for (int ks = 0; ks < 8; ks++) {
            const float2 v0 = *(const float2*)(xr0 + 16 * ks);
            const float2 v1 = *(const float2*)(xr1 + 16 * ks);
            const float2 v2 = *(const float2*)(xr0 + 16 * ks + 8);
            const float2 v3 = *(const float2*)(xr1 + 16 * ks + 8);
            __nv_bfloat162 b0 = __float22bfloat162_rn(v0);
            __nv_bfloat162 b1 = __float22bfloat162_rn(v1);
            __nv_bfloat162 b2 = __float22bfloat162_rn(v2);
            __nv_bfloat162 b3 = __float22bfloat162_rn(v3);
            afr[ks][0] = *(uint32_t*)&b0;
            afr[ks][1] = *(uint32_t*)&b1;
            afr[ks][2] = *(uint32_t*)&b2;
            afr[ks][3] = *(uint32_t*)&b3;
        }
    }

    float rmax[2];
    rmax[0] = -FLT_MAX; rmax[1] = -FLT_MAX;

    const int row8  = lane & 7;
    const int ctile = (lane >> 4) & 1;
    const int khalf = (lane >> 3) & 1;

    for (int c = 0; c < 16; c++) {    // 16 chunks of 64 codes
        const int buf = c & 1;
        asm volatile("cp.async.wait_group 0;" ::: "memory");
        __syncthreads();              // buffer `buf` ready; buffer buf^1 free
        if (c < 15) PREFETCH(c + 1, buf ^ 1);

        const uint32_t smEb = smEbase + buf * 16384;
        float acc[2][4];
        float sc[2][4];

        if (c == 0) {
            // Max-only warm-up over chunk 0 (no appends).
            #pragma unroll
            for (int b = 0; b < 4; b++) {
                BATCH_MMA(b);
                BATCH_SCORES(b);
                #pragma unroll
                for (int h = 0; h < 2; h++)
                    rmax[h] = fmaxf(rmax[h],
                                    fmaxf(fmaxf(sc[h][0], sc[h][1]),
                                          fmaxf(sc[h][2], sc[h][3])));
            }
            #pragma unroll
            for (int i = 0; i < 2; i++) {
                float v = rmax[i];
                v = fmaxf(v, __shfl_xor_sync(0xffffffffu, v, 1));
                v = fmaxf(v, __shfl_xor_sync(0xffffffffu, v, 2));
                rmax[i] = v;
            }
        }

        #pragma unroll
        for (int b = 0; b < 4; b++) {
            BATCH_MMA(b);
            BATCH_SCORES(b);

            // Two-level screening: compare the per-row batch max once.
            #pragma unroll
            for (int h = 0; h < 2; h++) {
                const float thr = rmax[h] - SCREEN_T;
                const float m = fmaxf(fmaxf(sc[h][0], sc[h][1]),
                                      fmaxf(sc[h][2], sc[h][3]));
                if (m >= thr) {    // rare
                    const int lr = wid * 16 + h * 8 + g;
                    #pragma unroll
                    for (int n2 = 0; n2 < 2; n2++)
                        #pragma unroll
                        for (int j = 0; j < 2; j++)
                            if (sc[h][n2 * 2 + j] >= thr) {
                                uint32_t n = atomicAdd(&sCnt[lr], 1u);
                                if (n < CAND_CAP)
                                    sCand[lr * CAND_CAP + n] =
                                        (uint16_t)(c * 64 + b * 16 + n2 * 8 + 2 * tig + j);
                            }
                }
                rmax[h] = fmaxf(rmax[h], m);
            }
        }

        #pragma unroll
        for (int i = 0; i < 2; i++) {
            float v = rmax[i];
            v = fmaxf(v, __shfl_xor_sync(0xffffffffu, v, 1));
            v = fmaxf(v, __shfl_xor_sync(0xffffffffu, v, 2));
            rmax[i] = v;
        }
    }
    __syncthreads();

    // Exact fp32 rescore: 8-lane quad per candidate.
    // dist' = 2*dot - ee (the -xx term is row-constant: argmax-equivalent).
    {
        const int ql = lane & 7;
        const int q  = lane >> 3;
        for (int rr = 0; rr < 16; rr++) {
            const int lr  = wid * 16 + rr;
            const int row = blockIdx.x * 128 + lr;
            const int cnt = (int)sCnt[lr];

            float bestv = -FLT_MAX;
            int   bestk = 0x7FFFFFFF;

            if (cnt <= CAND_CAP) {
                float4 xa[4];
                const float4* xr = (const float4*)(x + (size_t)row * DDIM);
                #pragma unroll
                for (int it = 0; it < 4; it++) xa[it] = xr[it * 8 + ql];

                for (int j0 = 0; j0 < cnt; j0 += 4) {
                    const int j  = j0 + q;
                    const int jc = (j < cnt) ? j : (cnt - 1);
                    const int kq = sCand[lr * CAND_CAP + jc];
                    const float4* er = (const float4*)(embed + (size_t)kq * DDIM);
                    float a0 = 0.f, a1 = 0.f, a2 = 0.f, a3 = 0.f;
                    #pragma unroll
                    for (int it = 0; it < 4; it++) {
                        const float4 ea = er[it * 8 + ql];
                        a0 = fmaf(xa[it].x, ea.x, a0);
                        a1 = fmaf(xa[it].y, ea.y, a1);
                        a2 = fmaf(xa[it].z, ea.z, a2);
                        a3 = fmaf(xa[it].w, ea.w, a3);
                    }
                    float part = (a0 + a1) + (a2 + a3);
                    part += __shfl_xor_sync(0xffffffffu, part, 1);
                    part += __shfl_xor_sync(0xffffffffu, part, 2);
                    part += __shfl_xor_sync(0xffffffffu, part, 4);
                    const float dist = 2.0f * part - g_ee[kq];
                    if (j < cnt &&
                        (dist > bestv || (dist == bestv && kq < bestk))) {
                        bestv = dist; bestk = kq;
                    }
                }
            } else {
                const float4* xr = (const float4*)(x + (size_t)row * DDIM);
                for (int k = lane; k < KCODES; k += 32) {
                    const float4* er = (const float4*)(embed + (size_t)k * DDIM);
                    float a0 = 0.f, a1 = 0.f, a2 = 0.f, a3 = 0.f;
                    #pragma unroll 8
                    for (int i = 0; i < 32; i++) {
                        float4 va = xr[i], ea = er[i];
                        a0 = fmaf(va.x, ea.x, a0);
                        a1 = fmaf(va.y, ea.y, a1);
                        a2 = fmaf(va.z, ea.z, a2);
                        a3 = fmaf(va.w, ea.w, a3);
                    }
                    const float dist = 2.0f * ((a0 + a1) + (a2 + a3)) - g_ee[k];
                    if (dist > bestv || (dist == bestv && k < bestk)) {
                        bestv = dist; bestk = k;
                    }
                }
                #pragma unroll
                for (int o = 1; o <= 4; o <<= 1) {
                    const float ov = __shfl_xor_sync(0xffffffffu, bestv, o);
                    const int   ok = __shfl_xor_sync(0xffffffffu, bestk, o);
                    if (ov > bestv || (ov == bestv && ok < bestk)) { bestv = ov; bestk = ok; }
                }
            }

            #pragma unroll
            for (int o = 8; o <= 16; o <<= 1) {
                const float ov = __shfl_xor_sync(0xffffffffu, bestv, o);
                const int   ok = __shfl_xor_sync(0xffffffffu, bestk, o);
                if (ov > bestv || (ov == bestv && ok < bestk)) { bestv = ov; bestk = ok; }
            }
            if (lane == 0) {
                fidx[lr] = bestk;
                out[IND_OFF + (size_t)row] = (float)bestk;
            }
        }
    }
    __syncthreads();

    // Fused epilogue: quantized = embed[idx] write + EMA scatter (RED).
    for (int v = tid; v < 128 * 32; v += 256) {
        const int r = v >> 5, seg = v & 31;
        const int idx = fidx[r];
        const float4* ep = (const float4*)(embed + (size_t)idx * DDIM);
        ((float4*)out)[(size_t)(blockIdx.x * 128 + r) * 32 + seg] = ep[seg];

        const float4 xv =
            ((const float4*)(x + (size_t)(blockIdx.x * 128 + r) * DDIM))[seg];
        float* dst = &g_embed_sum[(size_t)idx * DDIM + seg * 4];
        asm volatile("red.global.add.v4.f32 [%0], {%1,%2,%3,%4};"
                     :: "l"(dst), "f"(xv.x), "f"(xv.y), "f"(xv.z), "f"(xv.w)
                     : "memory");
    }
    if (tid < 128) atomicAdd(&g_counts[fidx[tid]], 1.0f);
}

// ---------------------------------------------------------------------------
// Final epilogue: new_cluster_size (+ redundant per-block total), new_embed_avg,
// new_embed. Block k handles code k.
__global__ void k_cfin(const float* __restrict__ cs,
                       const float* __restrict__ ea,
                       float* __restrict__ out) {
    const int k = blockIdx.x;    // 1024
    const int d = threadIdx.x;   // 128

    float part = 0.0f;
    #pragma unroll
    for (int i = 0; i < 8; i++) {
        const int j = d + i * 128;
        part += cs[j] * DECAYF + OMDF * g_counts[j];
    }
    #pragma unroll
    for (int o = 16; o > 0; o >>= 1) part += __shfl_down_sync(0xffffffffu, part, o);
    __shared__ float s[4];
    if ((d & 31) == 0) s[d >> 5] = part;
    __syncthreads();
    const float total = s[0] + s[1] + s[2] + s[3];

    const float ncs = cs[k] * DECAYF + OMDF * g_counts[k];
    if (d == 0) out[NCS_OFF + (size_t)k] = ncs;

    const size_t off = (size_t)k * DDIM + d;
    const float nea = ea[off] * DECAYF + OMDF * g_embed_sum[off];
    out[NEA_OFF + off] = nea;
    const float sm = (ncs + EPSF) / (total + KEPSF) * total;
    out[EMB_OFF + off] = nea / sm;
}

// ---------------------------------------------------------------------------
extern "C" void kernel_launch(void* const* d_in, const int* in_sizes, int n_in,
                              void* d_out, int out_size) {
    const float* x  = (const float*)d_in[0];
    const float* e  = (const float*)d_in[1];
    const float* ea = (const float*)d_in[2];
    const float* cs = (const float*)d_in[3];
    float* out = (float*)d_out;

    k_init<<<KCODES, 128>>>(e);                 // launch 1 (init + packE)
    k_score<<<N_ROWS / 128, 256>>>(x, e, out);  // launch 2 (everything per-row)
    k_cfin<<<KCODES, 128>>>(cs, ea, out);       // launch 3 (EMA epilogue)
}